// round 3
// baseline (speedup 1.0000x reference)
#include <cuda_runtime.h>

#define N_NODES 100000
#define N_EDGES 1600000
#define R 4
#define NG 256
#define SEG (N_NODES * R)
#define SCAN_B 1024
#define NBLK ((SEG + SCAN_B - 1) / SCAN_B)

// ---- scratch ----
__device__ int      g_cnt[SEG];
__device__ int      g_off[SEG + 1];
__device__ int      g_fill[SEG];
__device__ int      g_partial[NBLK];
__device__ int      g_esrc[N_EDGES];
__device__ float    g_h1[N_NODES * 16];
__device__ float    g_h2[N_NODES * 32];
__device__ float    g_h3[N_NODES * 64];
__device__ unsigned g_pool[NG * 64];

__device__ __forceinline__ unsigned enc(float v) {
    unsigned u = __float_as_uint(v);
    return (u & 0x80000000u) ? ~u : (u | 0x80000000u);
}
__device__ __forceinline__ float dec(unsigned u) {
    unsigned bits = (u & 0x80000000u) ? (u ^ 0x80000000u) : ~u;
    return __uint_as_float(bits);
}

__global__ void init_kernel() {
    int i = blockIdx.x * blockDim.x + threadIdx.x;
    if (i < SEG) g_cnt[i] = 0;
    if (i < NG * 64) g_pool[i] = 0x007FFFFFu;   // enc(-inf)
}

__global__ void count_kernel(const int* __restrict__ dst,
                             const int* __restrict__ et) {
    int e = blockIdx.x * blockDim.x + threadIdx.x;
    if (e < N_EDGES) atomicAdd(&g_cnt[dst[e] * R + et[e]], 1);
}

__global__ void scan1_kernel() {
    __shared__ int s[SCAN_B];
    int i = blockIdx.x * SCAN_B + threadIdx.x;
    int v = (i < SEG) ? g_cnt[i] : 0;
    s[threadIdx.x] = v;
    __syncthreads();
    for (int d = 1; d < SCAN_B; d <<= 1) {
        int t = (threadIdx.x >= d) ? s[threadIdx.x - d] : 0;
        __syncthreads();
        s[threadIdx.x] += t;
        __syncthreads();
    }
    if (i < SEG) g_off[i] = s[threadIdx.x] - v;
    if (threadIdx.x == SCAN_B - 1) g_partial[blockIdx.x] = s[threadIdx.x];
}

__global__ void scan2_kernel() {
    __shared__ int s[512];
    int v = (threadIdx.x < NBLK) ? g_partial[threadIdx.x] : 0;
    s[threadIdx.x] = v;
    __syncthreads();
    for (int d = 1; d < 512; d <<= 1) {
        int t = (threadIdx.x >= d) ? s[threadIdx.x - d] : 0;
        __syncthreads();
        s[threadIdx.x] += t;
        __syncthreads();
    }
    if (threadIdx.x < NBLK) g_partial[threadIdx.x] = s[threadIdx.x] - v;
}

__global__ void scan3_kernel() {
    int i = blockIdx.x * blockDim.x + threadIdx.x;
    if (i < SEG) {
        int o = g_off[i] + g_partial[i / SCAN_B];
        g_off[i]  = o;
        g_fill[i] = o;          // fill cursor pre-seeded with offset
    }
    if (i == 0) g_off[SEG] = N_EDGES;
}

__global__ void fill_kernel(const int* __restrict__ src,
                            const int* __restrict__ dst,
                            const int* __restrict__ et) {
    int e = blockIdx.x * blockDim.x + threadIdx.x;
    if (e < N_EDGES) {
        int sg  = dst[e] * R + et[e];
        int pos = atomicAdd(&g_fill[sg], 1);
        g_esrc[pos] = src[e];
    }
}

// ============================================================================
// Fused layer: warp-per-node edge-parallel gather + NPT-node register-tiled
// transform.  sAcc[node][r][DIN] with r==R holding the self (root) row.
// ============================================================================
template <int DIN, int DOUT, int NB, bool RELU>
__global__ __launch_bounds__(256) void layer_kernel(
        const float* __restrict__ xin,
        const float* __restrict__ W,     // [R, DIN, DOUT]
        const float* __restrict__ root,  // [DIN, DOUT]
        const float* __restrict__ bias,  // [DOUT]
        float* __restrict__ hout) {
    constexpr int FCH   = DIN / 4;        // float4 chunks per row
    constexpr int SLOTS = 32 / FCH;       // edges in flight per warp
    constexpr int OC    = DOUT / 4;       // output chunks
    constexpr int NGRP  = 256 / OC;       // node groups in transform
    constexpr int NPT   = NB / NGRP;      // nodes per thread in transform
    constexpr int WSZ   = (R + 1) * DIN * DOUT;
    static_assert(NB % 8 == 0 && NGRP * NPT == NB, "mapping");

    __shared__ float sAcc[NB][R + 1][DIN];
    __shared__ float sW[WSZ];
    __shared__ float sBias[DOUT];

    for (int i = threadIdx.x; i < R * DIN * DOUT; i += 256) sW[i] = W[i];
    for (int i = threadIdx.x; i < DIN * DOUT; i += 256)
        sW[R * DIN * DOUT + i] = root[i];
    if (threadIdx.x < DOUT) sBias[threadIdx.x] = bias[threadIdx.x];

    const int node0 = blockIdx.x * NB;
    const int wid  = threadIdx.x >> 5;
    const int lane = threadIdx.x & 31;
    const int slot = lane / FCH;
    const int feat = lane % FCH;

    // ---- gather: each warp handles nodes wid, wid+8, ... ----
    for (int nn = wid; nn < NB; nn += 8) {
        int n = node0 + nn;
        if (n >= N_NODES) break;
        int sb = n * R;
        int o0 = g_off[sb];
        int b1 = g_off[sb + 1];
        int b2 = g_off[sb + 2];
        int b3 = g_off[sb + 3];
        int e4 = g_off[sb + 4];

        float4 a0 = make_float4(0.f, 0.f, 0.f, 0.f), a1 = a0, a2 = a0, a3 = a0;

        for (int p0 = o0; p0 < e4; p0 += SLOTS) {
            int p = p0 + slot;
            if (p < e4) {
                int s = g_esrc[p];
                int r = (p >= b1) + (p >= b2) + (p >= b3);
                float4 v = *reinterpret_cast<const float4*>(xin + s * DIN + feat * 4);
                float m0 = (r == 0) ? 1.f : 0.f;
                float m1 = (r == 1) ? 1.f : 0.f;
                float m2 = (r == 2) ? 1.f : 0.f;
                float m3 = (r == 3) ? 1.f : 0.f;
                a0.x = fmaf(m0, v.x, a0.x); a0.y = fmaf(m0, v.y, a0.y);
                a0.z = fmaf(m0, v.z, a0.z); a0.w = fmaf(m0, v.w, a0.w);
                a1.x = fmaf(m1, v.x, a1.x); a1.y = fmaf(m1, v.y, a1.y);
                a1.z = fmaf(m1, v.z, a1.z); a1.w = fmaf(m1, v.w, a1.w);
                a2.x = fmaf(m2, v.x, a2.x); a2.y = fmaf(m2, v.y, a2.y);
                a2.z = fmaf(m2, v.z, a2.z); a2.w = fmaf(m2, v.w, a2.w);
                a3.x = fmaf(m3, v.x, a3.x); a3.y = fmaf(m3, v.y, a3.y);
                a3.z = fmaf(m3, v.z, a3.z); a3.w = fmaf(m3, v.w, a3.w);
            }
        }
        // reduce across slots (lanes FCH apart)
#pragma unroll
        for (int m = FCH; m < 32; m <<= 1) {
            a0.x += __shfl_xor_sync(~0u, a0.x, m); a0.y += __shfl_xor_sync(~0u, a0.y, m);
            a0.z += __shfl_xor_sync(~0u, a0.z, m); a0.w += __shfl_xor_sync(~0u, a0.w, m);
            a1.x += __shfl_xor_sync(~0u, a1.x, m); a1.y += __shfl_xor_sync(~0u, a1.y, m);
            a1.z += __shfl_xor_sync(~0u, a1.z, m); a1.w += __shfl_xor_sync(~0u, a1.w, m);
            a2.x += __shfl_xor_sync(~0u, a2.x, m); a2.y += __shfl_xor_sync(~0u, a2.y, m);
            a2.z += __shfl_xor_sync(~0u, a2.z, m); a2.w += __shfl_xor_sync(~0u, a2.w, m);
            a3.x += __shfl_xor_sync(~0u, a3.x, m); a3.y += __shfl_xor_sync(~0u, a3.y, m);
            a3.z += __shfl_xor_sync(~0u, a3.z, m); a3.w += __shfl_xor_sync(~0u, a3.w, m);
        }
        if (slot == 0) {
            float i0 = __fdividef(1.f, fmaxf((float)(b1 - o0), 1.f));
            float i1 = __fdividef(1.f, fmaxf((float)(b2 - b1), 1.f));
            float i2 = __fdividef(1.f, fmaxf((float)(b3 - b2), 1.f));
            float i3 = __fdividef(1.f, fmaxf((float)(e4 - b3), 1.f));
            a0.x *= i0; a0.y *= i0; a0.z *= i0; a0.w *= i0;
            a1.x *= i1; a1.y *= i1; a1.z *= i1; a1.w *= i1;
            a2.x *= i2; a2.y *= i2; a2.z *= i2; a2.w *= i2;
            a3.x *= i3; a3.y *= i3; a3.z *= i3; a3.w *= i3;
            *reinterpret_cast<float4*>(&sAcc[nn][0][feat * 4]) = a0;
            *reinterpret_cast<float4*>(&sAcc[nn][1][feat * 4]) = a1;
            *reinterpret_cast<float4*>(&sAcc[nn][2][feat * 4]) = a2;
            *reinterpret_cast<float4*>(&sAcc[nn][3][feat * 4]) = a3;
            // self row for the root transform
            *reinterpret_cast<float4*>(&sAcc[nn][R][feat * 4]) =
                *reinterpret_cast<const float4*>(xin + n * DIN + feat * 4);
        }
    }
    __syncthreads();

    // ---- transform: thread = (output chunk, node group of NPT nodes) ----
    {
        int oc  = threadIdx.x % OC;
        int grp = threadIdx.x / OC;
        int o0  = oc * 4;
        int nb0 = grp * NPT;

        float4 sum[NPT];
        float4 bv = *reinterpret_cast<const float4*>(&sBias[o0]);
#pragma unroll
        for (int k = 0; k < NPT; k++) sum[k] = bv;

#pragma unroll
        for (int r = 0; r < R + 1; r++) {
#pragma unroll
            for (int i4 = 0; i4 < DIN / 4; i4++) {
                const float* wb = &sW[(r * DIN + i4 * 4) * DOUT + o0];
                float4 w0 = *reinterpret_cast<const float4*>(wb);
                float4 w1 = *reinterpret_cast<const float4*>(wb + DOUT);
                float4 w2 = *reinterpret_cast<const float4*>(wb + 2 * DOUT);
                float4 w3 = *reinterpret_cast<const float4*>(wb + 3 * DOUT);
#pragma unroll
                for (int k = 0; k < NPT; k++) {
                    float4 a = *reinterpret_cast<const float4*>(&sAcc[nb0 + k][r][i4 * 4]);
                    sum[k].x += a.x * w0.x + a.y * w1.x + a.z * w2.x + a.w * w3.x;
                    sum[k].y += a.x * w0.y + a.y * w1.y + a.z * w2.y + a.w * w3.y;
                    sum[k].z += a.x * w0.z + a.y * w1.z + a.z * w2.z + a.w * w3.z;
                    sum[k].w += a.x * w0.w + a.y * w1.w + a.z * w2.w + a.w * w3.w;
                }
            }
        }
#pragma unroll
        for (int k = 0; k < NPT; k++) {
            int n = node0 + nb0 + k;
            if (n < N_NODES) {
                float4 s = sum[k];
                if (RELU) {
                    s.x = fmaxf(s.x, 0.f); s.y = fmaxf(s.y, 0.f);
                    s.z = fmaxf(s.z, 0.f); s.w = fmaxf(s.w, 0.f);
                }
                *reinterpret_cast<float4*>(&hout[n * DOUT + o0]) = s;
            }
        }
    }
}

// ---- strip-reduced max pooling (batch is sorted) ----
__global__ void pool_kernel(const int* __restrict__ batch) {
    int grp = threadIdx.x / 64;
    int c   = threadIdx.x % 64;
    int n0  = blockIdx.x * 256 + grp * 64;
    if (n0 >= N_NODES) return;
    int nend = min(n0 + 64, N_NODES);
    float cur = __int_as_float(0xff800000);
    int curb  = batch[n0];
    for (int n = n0; n < nend; n++) {
        int   b = batch[n];
        float v = g_h3[n * 64 + c];
        if (b != curb) {
            atomicMax(&g_pool[curb * 64 + c], enc(cur));
            cur = __int_as_float(0xff800000);
            curb = b;
        }
        cur = fmaxf(cur, v);
    }
    atomicMax(&g_pool[curb * 64 + c], enc(cur));
}

__global__ void decode_kernel(float* __restrict__ out) {
    int i = blockIdx.x * blockDim.x + threadIdx.x;
    if (i < NG * 64) out[i] = dec(g_pool[i]);
}

extern "C" void kernel_launch(void* const* d_in, const int* in_sizes, int n_in,
                              void* d_out, int out_size) {
    const float* x     = (const float*)d_in[0];
    const int*   ei    = (const int*)d_in[1];
    const int*   src   = ei;
    const int*   dst   = ei + N_EDGES;
    const int*   et    = (const int*)d_in[2];
    const int*   batch = (const int*)d_in[3];
    const float* W1 = (const float*)d_in[4];
    const float* r1 = (const float*)d_in[5];
    const float* b1 = (const float*)d_in[6];
    const float* W2 = (const float*)d_in[7];
    const float* r2 = (const float*)d_in[8];
    const float* b2 = (const float*)d_in[9];
    const float* W3 = (const float*)d_in[10];
    const float* r3 = (const float*)d_in[11];
    const float* b3 = (const float*)d_in[12];
    float* out = (float*)d_out;

    float *h1p, *h2p, *h3p;
    cudaGetSymbolAddress((void**)&h1p, g_h1);
    cudaGetSymbolAddress((void**)&h2p, g_h2);
    cudaGetSymbolAddress((void**)&h3p, g_h3);

    const int T = 256;

    init_kernel<<<(SEG + T - 1) / T, T>>>();
    count_kernel<<<(N_EDGES + T - 1) / T, T>>>(dst, et);
    scan1_kernel<<<NBLK, SCAN_B>>>();
    scan2_kernel<<<1, 512>>>();
    scan3_kernel<<<(SEG + T - 1) / T, T>>>();
    fill_kernel<<<(N_EDGES + T - 1) / T, T>>>(src, dst, et);

    layer_kernel<16, 16, 128, true ><<<(N_NODES + 127) / 128, T>>>(x,   W1, r1, b1, h1p);
    layer_kernel<16, 32, 128, true ><<<(N_NODES + 127) / 128, T>>>(h1p, W2, r2, b2, h2p);
    layer_kernel<32, 64,  64, false><<<(N_NODES +  63) /  64, T>>>(h2p, W3, r3, b3, h3p);

    pool_kernel<<<(N_NODES + 255) / 256, T>>>(batch);
    decode_kernel<<<(NG * 64 + T - 1) / T, T>>>(out);
}

// round 4
// speedup vs baseline: 1.0547x; 1.0547x over previous
#include <cuda_runtime.h>

#define N_NODES 100000
#define N_EDGES 1600000
#define R 4
#define NG 256
#define SEG (N_NODES * R)
#define SCAN_T 1024
#define NT2 ((SEG + SCAN_T - 1) / SCAN_T)   // 391 tiles

// ---- scratch ----
__device__ int      g_cnt[SEG];
__device__ int      g_off[SEG + 1];
__device__ int      g_fill[SEG];
__device__ int      g_esrc[N_EDGES];
__device__ unsigned long long g_state[NT2];
__device__ int      g_ticket;
__device__ float    g_h1[N_NODES * 16];
__device__ float    g_h2[N_NODES * 32];
__device__ float    g_h3[N_NODES * 64];
__device__ unsigned g_pool[NG * 64];

__device__ __forceinline__ unsigned enc(float v) {
    unsigned u = __float_as_uint(v);
    return (u & 0x80000000u) ? ~u : (u | 0x80000000u);
}
__device__ __forceinline__ float dec(unsigned u) {
    unsigned bits = (u & 0x80000000u) ? (u ^ 0x80000000u) : ~u;
    return __uint_as_float(bits);
}

// ---- init: zero counts, scan state, ticket; pool = enc(-inf) ----
__global__ void init_kernel() {
    int i = blockIdx.x * blockDim.x + threadIdx.x;
    if (i < SEG) g_cnt[i] = 0;
    if (i < NT2) g_state[i] = 0ull;
    if (i == 0)  g_ticket = 0;
    if (i < NG * 64) g_pool[i] = 0x007FFFFFu;
}

__global__ void count_kernel(const int* __restrict__ dst,
                             const int* __restrict__ et) {
    int e = blockIdx.x * blockDim.x + threadIdx.x;
    if (e < N_EDGES) atomicAdd(&g_cnt[dst[e] * R + et[e]], 1);
}

// ---- single-pass decoupled-lookback exclusive scan; seeds g_off/g_fill ----
__global__ __launch_bounds__(SCAN_T) void scan_kernel() {
    __shared__ int s[SCAN_T];
    __shared__ int s_tile;
    __shared__ int s_prefix;

    if (threadIdx.x == 0) s_tile = atomicAdd(&g_ticket, 1);
    __syncthreads();
    int tile = s_tile;
    int i = tile * SCAN_T + threadIdx.x;
    int v = (i < SEG) ? g_cnt[i] : 0;
    s[threadIdx.x] = v;
    __syncthreads();
    for (int d = 1; d < SCAN_T; d <<= 1) {
        int t = (threadIdx.x >= d) ? s[threadIdx.x - d] : 0;
        __syncthreads();
        s[threadIdx.x] += t;
        __syncthreads();
    }
    int incl  = s[threadIdx.x];
    int total = s[SCAN_T - 1];

    if (threadIdx.x == 0) {
        unsigned long long st = (tile == 0)
            ? ((2ull << 32) | (unsigned)total)
            : ((1ull << 32) | (unsigned)total);
        __threadfence();
        atomicExch(&g_state[tile], st);
        if (tile == 0) s_prefix = 0;
    }
    if (tile > 0 && threadIdx.x < 32) {
        int lane = threadIdx.x;
        int j = tile - 1;
        int agg = 0;
        while (true) {
            int idx = j - lane;
            unsigned long long st = (idx >= 0)
                ? atomicAdd(&g_state[idx], 0ull)
                : (2ull << 32);
            unsigned flag = (unsigned)(st >> 32);
            unsigned invm = __ballot_sync(0xffffffffu, flag == 0);
            if (invm) continue;                       // window not ready; retry
            unsigned prefm = __ballot_sync(0xffffffffu, flag == 2);
            int stop = prefm ? (__ffs(prefm) - 1) : 32;
            int contrib = (lane <= stop) ? (int)(st & 0xffffffffu) : 0;
#pragma unroll
            for (int m = 16; m; m >>= 1) contrib += __shfl_xor_sync(~0u, contrib, m);
            agg += contrib;
            if (stop < 32) break;
            j -= 32;
        }
        if (lane == 0) {
            s_prefix = agg;
            __threadfence();
            atomicExch(&g_state[tile], (2ull << 32) | (unsigned)(agg + total));
        }
    }
    __syncthreads();
    int prefix = s_prefix;
    if (i < SEG) {
        int o = prefix + incl - v;
        g_off[i]  = o;
        g_fill[i] = o;
    }
    if (i == SEG - 1) g_off[SEG] = N_EDGES;
}

__global__ void fill_kernel(const int* __restrict__ src,
                            const int* __restrict__ dst,
                            const int* __restrict__ et) {
    int e = blockIdx.x * blockDim.x + threadIdx.x;
    if (e < N_EDGES) {
        int sg  = dst[e] * R + et[e];
        int pos = atomicAdd(&g_fill[sg], 1);
        g_esrc[pos] = src[e];
    }
}

// ============================================================================
// Fused layer (round-3 structure, occupancy-tuned NB per layer)
// ============================================================================
template <int DIN, int DOUT, int NB, bool RELU>
__global__ __launch_bounds__(256) void layer_kernel(
        const float* __restrict__ xin,
        const float* __restrict__ W,
        const float* __restrict__ root,
        const float* __restrict__ bias,
        float* __restrict__ hout) {
    constexpr int FCH   = DIN / 4;
    constexpr int SLOTS = 32 / FCH;
    constexpr int OC    = DOUT / 4;
    constexpr int NGRP  = 256 / OC;
    constexpr int NPT   = NB / NGRP;
    constexpr int WSZ   = (R + 1) * DIN * DOUT;
    static_assert(NB % 8 == 0 && NGRP * NPT == NB, "mapping");

    __shared__ float sAcc[NB][R + 1][DIN];
    __shared__ float sW[WSZ];
    __shared__ float sBias[DOUT];

    for (int i = threadIdx.x; i < R * DIN * DOUT; i += 256) sW[i] = W[i];
    for (int i = threadIdx.x; i < DIN * DOUT; i += 256)
        sW[R * DIN * DOUT + i] = root[i];
    if (threadIdx.x < DOUT) sBias[threadIdx.x] = bias[threadIdx.x];

    const int node0 = blockIdx.x * NB;
    const int wid  = threadIdx.x >> 5;
    const int lane = threadIdx.x & 31;
    const int slot = lane / FCH;
    const int feat = lane % FCH;

    for (int nn = wid; nn < NB; nn += 8) {
        int n = node0 + nn;
        if (n >= N_NODES) break;
        int sb = n * R;
        int o0 = g_off[sb];
        int b1 = g_off[sb + 1];
        int b2 = g_off[sb + 2];
        int b3 = g_off[sb + 3];
        int e4 = g_off[sb + 4];

        float4 a0 = make_float4(0.f, 0.f, 0.f, 0.f), a1 = a0, a2 = a0, a3 = a0;

        for (int p0 = o0; p0 < e4; p0 += SLOTS) {
            int p = p0 + slot;
            if (p < e4) {
                int s = g_esrc[p];
                int r = (p >= b1) + (p >= b2) + (p >= b3);
                float4 v = *reinterpret_cast<const float4*>(xin + s * DIN + feat * 4);
                float m0 = (r == 0) ? 1.f : 0.f;
                float m1 = (r == 1) ? 1.f : 0.f;
                float m2 = (r == 2) ? 1.f : 0.f;
                float m3 = (r == 3) ? 1.f : 0.f;
                a0.x = fmaf(m0, v.x, a0.x); a0.y = fmaf(m0, v.y, a0.y);
                a0.z = fmaf(m0, v.z, a0.z); a0.w = fmaf(m0, v.w, a0.w);
                a1.x = fmaf(m1, v.x, a1.x); a1.y = fmaf(m1, v.y, a1.y);
                a1.z = fmaf(m1, v.z, a1.z); a1.w = fmaf(m1, v.w, a1.w);
                a2.x = fmaf(m2, v.x, a2.x); a2.y = fmaf(m2, v.y, a2.y);
                a2.z = fmaf(m2, v.z, a2.z); a2.w = fmaf(m2, v.w, a2.w);
                a3.x = fmaf(m3, v.x, a3.x); a3.y = fmaf(m3, v.y, a3.y);
                a3.z = fmaf(m3, v.z, a3.z); a3.w = fmaf(m3, v.w, a3.w);
            }
        }
#pragma unroll
        for (int m = FCH; m < 32; m <<= 1) {
            a0.x += __shfl_xor_sync(~0u, a0.x, m); a0.y += __shfl_xor_sync(~0u, a0.y, m);
            a0.z += __shfl_xor_sync(~0u, a0.z, m); a0.w += __shfl_xor_sync(~0u, a0.w, m);
            a1.x += __shfl_xor_sync(~0u, a1.x, m); a1.y += __shfl_xor_sync(~0u, a1.y, m);
            a1.z += __shfl_xor_sync(~0u, a1.z, m); a1.w += __shfl_xor_sync(~0u, a1.w, m);
            a2.x += __shfl_xor_sync(~0u, a2.x, m); a2.y += __shfl_xor_sync(~0u, a2.y, m);
            a2.z += __shfl_xor_sync(~0u, a2.z, m); a2.w += __shfl_xor_sync(~0u, a2.w, m);
            a3.x += __shfl_xor_sync(~0u, a3.x, m); a3.y += __shfl_xor_sync(~0u, a3.y, m);
            a3.z += __shfl_xor_sync(~0u, a3.z, m); a3.w += __shfl_xor_sync(~0u, a3.w, m);
        }
        if (slot == 0) {
            float i0 = __fdividef(1.f, fmaxf((float)(b1 - o0), 1.f));
            float i1 = __fdividef(1.f, fmaxf((float)(b2 - b1), 1.f));
            float i2 = __fdividef(1.f, fmaxf((float)(b3 - b2), 1.f));
            float i3 = __fdividef(1.f, fmaxf((float)(e4 - b3), 1.f));
            a0.x *= i0; a0.y *= i0; a0.z *= i0; a0.w *= i0;
            a1.x *= i1; a1.y *= i1; a1.z *= i1; a1.w *= i1;
            a2.x *= i2; a2.y *= i2; a2.z *= i2; a2.w *= i2;
            a3.x *= i3; a3.y *= i3; a3.z *= i3; a3.w *= i3;
            *reinterpret_cast<float4*>(&sAcc[nn][0][feat * 4]) = a0;
            *reinterpret_cast<float4*>(&sAcc[nn][1][feat * 4]) = a1;
            *reinterpret_cast<float4*>(&sAcc[nn][2][feat * 4]) = a2;
            *reinterpret_cast<float4*>(&sAcc[nn][3][feat * 4]) = a3;
            *reinterpret_cast<float4*>(&sAcc[nn][R][feat * 4]) =
                *reinterpret_cast<const float4*>(xin + n * DIN + feat * 4);
        }
    }
    __syncthreads();

    {
        int oc  = threadIdx.x % OC;
        int grp = threadIdx.x / OC;
        int o0  = oc * 4;
        int nb0 = grp * NPT;

        float4 sum[NPT];
        float4 bv = *reinterpret_cast<const float4*>(&sBias[o0]);
#pragma unroll
        for (int k = 0; k < NPT; k++) sum[k] = bv;

#pragma unroll
        for (int r = 0; r < R + 1; r++) {
#pragma unroll
            for (int i4 = 0; i4 < DIN / 4; i4++) {
                const float* wb = &sW[(r * DIN + i4 * 4) * DOUT + o0];
                float4 w0 = *reinterpret_cast<const float4*>(wb);
                float4 w1 = *reinterpret_cast<const float4*>(wb + DOUT);
                float4 w2 = *reinterpret_cast<const float4*>(wb + 2 * DOUT);
                float4 w3 = *reinterpret_cast<const float4*>(wb + 3 * DOUT);
#pragma unroll
                for (int k = 0; k < NPT; k++) {
                    float4 a = *reinterpret_cast<const float4*>(&sAcc[nb0 + k][r][i4 * 4]);
                    sum[k].x += a.x * w0.x + a.y * w1.x + a.z * w2.x + a.w * w3.x;
                    sum[k].y += a.x * w0.y + a.y * w1.y + a.z * w2.y + a.w * w3.y;
                    sum[k].z += a.x * w0.z + a.y * w1.z + a.z * w2.z + a.w * w3.z;
                    sum[k].w += a.x * w0.w + a.y * w1.w + a.z * w2.w + a.w * w3.w;
                }
            }
        }
#pragma unroll
        for (int k = 0; k < NPT; k++) {
            int n = node0 + nb0 + k;
            if (n < N_NODES) {
                float4 sv = sum[k];
                if (RELU) {
                    sv.x = fmaxf(sv.x, 0.f); sv.y = fmaxf(sv.y, 0.f);
                    sv.z = fmaxf(sv.z, 0.f); sv.w = fmaxf(sv.w, 0.f);
                }
                *reinterpret_cast<float4*>(&hout[n * DOUT + o0]) = sv;
            }
        }
    }
}

// ---- strip-reduced max pooling ----
__global__ void pool_kernel(const int* __restrict__ batch) {
    int grp = threadIdx.x / 64;
    int c   = threadIdx.x % 64;
    int n0  = blockIdx.x * 256 + grp * 64;
    if (n0 >= N_NODES) return;
    int nend = min(n0 + 64, N_NODES);
    float cur = __int_as_float(0xff800000);
    int curb  = batch[n0];
    for (int n = n0; n < nend; n++) {
        int   b = batch[n];
        float v = g_h3[n * 64 + c];
        if (b != curb) {
            atomicMax(&g_pool[curb * 64 + c], enc(cur));
            cur = __int_as_float(0xff800000);
            curb = b;
        }
        cur = fmaxf(cur, v);
    }
    atomicMax(&g_pool[curb * 64 + c], enc(cur));
}

__global__ void decode_kernel(float* __restrict__ out) {
    int i = blockIdx.x * blockDim.x + threadIdx.x;
    if (i < NG * 64) out[i] = dec(g_pool[i]);
}

extern "C" void kernel_launch(void* const* d_in, const int* in_sizes, int n_in,
                              void* d_out, int out_size) {
    const float* x     = (const float*)d_in[0];
    const int*   ei    = (const int*)d_in[1];
    const int*   src   = ei;
    const int*   dst   = ei + N_EDGES;
    const int*   et    = (const int*)d_in[2];
    const int*   batch = (const int*)d_in[3];
    const float* W1 = (const float*)d_in[4];
    const float* r1 = (const float*)d_in[5];
    const float* b1 = (const float*)d_in[6];
    const float* W2 = (const float*)d_in[7];
    const float* r2 = (const float*)d_in[8];
    const float* b2 = (const float*)d_in[9];
    const float* W3 = (const float*)d_in[10];
    const float* r3 = (const float*)d_in[11];
    const float* b3 = (const float*)d_in[12];
    float* out = (float*)d_out;

    float *h1p, *h2p, *h3p;
    cudaGetSymbolAddress((void**)&h1p, g_h1);
    cudaGetSymbolAddress((void**)&h2p, g_h2);
    cudaGetSymbolAddress((void**)&h3p, g_h3);

    const int T = 256;

    init_kernel<<<(SEG + T - 1) / T, T>>>();                       // 1
    count_kernel<<<(N_EDGES + T - 1) / T, T>>>(dst, et);           // 2
    scan_kernel<<<NT2, SCAN_T>>>();                                // 3
    fill_kernel<<<(N_EDGES + T - 1) / T, T>>>(src, dst, et);       // 4 <- profiled

    layer_kernel<16, 16, 64, true ><<<(N_NODES + 63) / 64, T>>>(x,   W1, r1, b1, h1p);
    layer_kernel<16, 32, 64, true ><<<(N_NODES + 63) / 64, T>>>(h1p, W2, r2, b2, h2p);
    layer_kernel<32, 64, 32, false><<<(N_NODES + 31) / 32, T>>>(h2p, W3, r3, b3, h3p);

    pool_kernel<<<(N_NODES + 255) / 256, T>>>(batch);
    decode_kernel<<<(NG * 64 + T - 1) / T, T>>>(out);
}

// round 5
// speedup vs baseline: 1.0645x; 1.0093x over previous
#include <cuda_runtime.h>

#define N_NODES 100000
#define N_EDGES 1600000
#define R 4
#define NG 256
#define SEG (N_NODES * R)
#define SCAN_T 1024
#define NT2 ((SEG + SCAN_T - 1) / SCAN_T)   // 391 tiles

// ---- scratch (zero-initialized at module load; every launch self-restores) ----
__device__ int      g_cnt[SEG];          // zeroed by scan_kernel each launch
__device__ int      g_off[SEG + 1];
__device__ int      g_fill[SEG];
__device__ int      g_esrc[N_EDGES];
__device__ unsigned long long g_state[NT2];  // reset by fill_kernel
__device__ int      g_ticket;                // reset by fill_kernel
__device__ float    g_h1[N_NODES * 16];
__device__ float    g_h2[N_NODES * 32];
__device__ float    g_h3[N_NODES * 64];
__device__ unsigned g_pool[NG * 64];         // reset by decode_kernel

__device__ __forceinline__ unsigned enc(float v) {
    unsigned u = __float_as_uint(v);
    return (u & 0x80000000u) ? ~u : (u | 0x80000000u);
}
__device__ __forceinline__ float dec(unsigned u) {
    unsigned bits = (u & 0x80000000u) ? (u ^ 0x80000000u) : ~u;
    return __uint_as_float(bits);
}

// ---- 1. count edges per (dst, relation) ----
__global__ void count_kernel(const int* __restrict__ dst,
                             const int* __restrict__ et) {
    int e = blockIdx.x * blockDim.x + threadIdx.x;
    if (e < N_EDGES) atomicAdd(&g_cnt[dst[e] * R + et[e]], 1);
}

// ---- 2. single-pass decoupled-lookback scan; seeds off/fill; zeroes cnt ----
__global__ __launch_bounds__(SCAN_T) void scan_kernel() {
    __shared__ int s[SCAN_T];
    __shared__ int s_tile;
    __shared__ int s_prefix;

    if (threadIdx.x == 0) s_tile = atomicAdd(&g_ticket, 1);
    __syncthreads();
    int tile = s_tile;
    int i = tile * SCAN_T + threadIdx.x;
    int v = (i < SEG) ? g_cnt[i] : 0;
    s[threadIdx.x] = v;
    __syncthreads();
    for (int d = 1; d < SCAN_T; d <<= 1) {
        int t = (threadIdx.x >= d) ? s[threadIdx.x - d] : 0;
        __syncthreads();
        s[threadIdx.x] += t;
        __syncthreads();
    }
    int incl  = s[threadIdx.x];
    int total = s[SCAN_T - 1];

    if (threadIdx.x == 0) {
        unsigned long long st = (tile == 0)
            ? ((2ull << 32) | (unsigned)total)
            : ((1ull << 32) | (unsigned)total);
        __threadfence();
        atomicExch(&g_state[tile], st);
        if (tile == 0) s_prefix = 0;
    }
    if (tile > 0 && threadIdx.x < 32) {
        int lane = threadIdx.x;
        int j = tile - 1;
        int agg = 0;
        while (true) {
            int idx = j - lane;
            unsigned long long st = (idx >= 0)
                ? atomicAdd(&g_state[idx], 0ull)
                : (2ull << 32);
            unsigned flag = (unsigned)(st >> 32);
            unsigned invm = __ballot_sync(0xffffffffu, flag == 0);
            if (invm) continue;
            unsigned prefm = __ballot_sync(0xffffffffu, flag == 2);
            int stop = prefm ? (__ffs(prefm) - 1) : 32;
            int contrib = (lane <= stop) ? (int)(st & 0xffffffffu) : 0;
#pragma unroll
            for (int m = 16; m; m >>= 1) contrib += __shfl_xor_sync(~0u, contrib, m);
            agg += contrib;
            if (stop < 32) break;
            j -= 32;
        }
        if (lane == 0) {
            s_prefix = agg;
            __threadfence();
            atomicExch(&g_state[tile], (2ull << 32) | (unsigned)(agg + total));
        }
    }
    __syncthreads();
    int prefix = s_prefix;
    if (i < SEG) {
        int o = prefix + incl - v;
        g_off[i]  = o;
        g_fill[i] = o;
        g_cnt[i]  = 0;                 // restore for next launch
    }
    if (i == SEG - 1) g_off[SEG] = N_EDGES;
}

// ---- 3. fill CSR; restore scan state for next launch ----
__global__ void fill_kernel(const int* __restrict__ src,
                            const int* __restrict__ dst,
                            const int* __restrict__ et) {
    int e = blockIdx.x * blockDim.x + threadIdx.x;
    if (e < N_EDGES) {
        int sg  = dst[e] * R + et[e];
        int pos = atomicAdd(&g_fill[sg], 1);
        g_esrc[pos] = src[e];
    }
    if (e < NT2) g_state[e] = 0ull;
    if (e == 0)  g_ticket = 0;
}

// ============================================================================
// Fused layer, register-dieted: __launch_bounds__(256, 5) -> <=51 regs.
// ============================================================================
template <int DIN, int DOUT, int NB, bool RELU>
__global__ __launch_bounds__(256, 5) void layer_kernel(
        const float* __restrict__ xin,
        const float* __restrict__ W,
        const float* __restrict__ root,
        const float* __restrict__ bias,
        float* __restrict__ hout) {
    constexpr int FCH   = DIN / 4;
    constexpr int SLOTS = 32 / FCH;
    constexpr int OC    = DOUT / 4;
    constexpr int NGRP  = 256 / OC;
    constexpr int NPT   = NB / NGRP;
    constexpr int WSZ   = (R + 1) * DIN * DOUT;
    static_assert(NB % 8 == 0 && NGRP * NPT == NB, "mapping");

    __shared__ float sAcc[NB][R + 1][DIN];
    __shared__ float sW[WSZ];
    __shared__ float sBias[DOUT];

    for (int i = threadIdx.x; i < R * DIN * DOUT; i += 256) sW[i] = W[i];
    for (int i = threadIdx.x; i < DIN * DOUT; i += 256)
        sW[R * DIN * DOUT + i] = root[i];
    if (threadIdx.x < DOUT) sBias[threadIdx.x] = bias[threadIdx.x];

    const int node0 = blockIdx.x * NB;
    const int wid  = threadIdx.x >> 5;
    const int lane = threadIdx.x & 31;
    const int slot = lane / FCH;
    const int feat = lane % FCH;

    for (int nn = wid; nn < NB; nn += 8) {
        int n = node0 + nn;
        if (n >= N_NODES) break;
        int sb = n * R;
        int o0 = g_off[sb];
        int b1 = g_off[sb + 1];
        int b2 = g_off[sb + 2];
        int b3 = g_off[sb + 3];
        int e4 = g_off[sb + 4];

        float4 a0 = make_float4(0.f, 0.f, 0.f, 0.f), a1 = a0, a2 = a0, a3 = a0;

        for (int p0 = o0; p0 < e4; p0 += SLOTS) {
            int p = p0 + slot;
            if (p < e4) {
                int s = g_esrc[p];
                float4 v = *reinterpret_cast<const float4*>(xin + s * DIN + feat * 4);
                int r = (p >= b1) + (p >= b2) + (p >= b3);
                float m0 = (r == 0) ? 1.f : 0.f;
                float m1 = (r == 1) ? 1.f : 0.f;
                float m2 = (r == 2) ? 1.f : 0.f;
                float m3 = (r == 3) ? 1.f : 0.f;
                a0.x = fmaf(m0, v.x, a0.x); a0.y = fmaf(m0, v.y, a0.y);
                a0.z = fmaf(m0, v.z, a0.z); a0.w = fmaf(m0, v.w, a0.w);
                a1.x = fmaf(m1, v.x, a1.x); a1.y = fmaf(m1, v.y, a1.y);
                a1.z = fmaf(m1, v.z, a1.z); a1.w = fmaf(m1, v.w, a1.w);
                a2.x = fmaf(m2, v.x, a2.x); a2.y = fmaf(m2, v.y, a2.y);
                a2.z = fmaf(m2, v.z, a2.z); a2.w = fmaf(m2, v.w, a2.w);
                a3.x = fmaf(m3, v.x, a3.x); a3.y = fmaf(m3, v.y, a3.y);
                a3.z = fmaf(m3, v.z, a3.z); a3.w = fmaf(m3, v.w, a3.w);
            }
        }
#pragma unroll
        for (int m = FCH; m < 32; m <<= 1) {
            a0.x += __shfl_xor_sync(~0u, a0.x, m); a0.y += __shfl_xor_sync(~0u, a0.y, m);
            a0.z += __shfl_xor_sync(~0u, a0.z, m); a0.w += __shfl_xor_sync(~0u, a0.w, m);
            a1.x += __shfl_xor_sync(~0u, a1.x, m); a1.y += __shfl_xor_sync(~0u, a1.y, m);
            a1.z += __shfl_xor_sync(~0u, a1.z, m); a1.w += __shfl_xor_sync(~0u, a1.w, m);
            a2.x += __shfl_xor_sync(~0u, a2.x, m); a2.y += __shfl_xor_sync(~0u, a2.y, m);
            a2.z += __shfl_xor_sync(~0u, a2.z, m); a2.w += __shfl_xor_sync(~0u, a2.w, m);
            a3.x += __shfl_xor_sync(~0u, a3.x, m); a3.y += __shfl_xor_sync(~0u, a3.y, m);
            a3.z += __shfl_xor_sync(~0u, a3.z, m); a3.w += __shfl_xor_sync(~0u, a3.w, m);
        }
        if (slot == 0) {
            float i0 = __fdividef(1.f, fmaxf((float)(b1 - o0), 1.f));
            float i1 = __fdividef(1.f, fmaxf((float)(b2 - b1), 1.f));
            float i2 = __fdividef(1.f, fmaxf((float)(b3 - b2), 1.f));
            float i3 = __fdividef(1.f, fmaxf((float)(e4 - b3), 1.f));
            a0.x *= i0; a0.y *= i0; a0.z *= i0; a0.w *= i0;
            a1.x *= i1; a1.y *= i1; a1.z *= i1; a1.w *= i1;
            a2.x *= i2; a2.y *= i2; a2.z *= i2; a2.w *= i2;
            a3.x *= i3; a3.y *= i3; a3.z *= i3; a3.w *= i3;
            *reinterpret_cast<float4*>(&sAcc[nn][0][feat * 4]) = a0;
            *reinterpret_cast<float4*>(&sAcc[nn][1][feat * 4]) = a1;
            *reinterpret_cast<float4*>(&sAcc[nn][2][feat * 4]) = a2;
            *reinterpret_cast<float4*>(&sAcc[nn][3][feat * 4]) = a3;
            *reinterpret_cast<float4*>(&sAcc[nn][R][feat * 4]) =
                *reinterpret_cast<const float4*>(xin + n * DIN + feat * 4);
        }
    }
    __syncthreads();

    {
        int oc  = threadIdx.x % OC;
        int grp = threadIdx.x / OC;
        int o0  = oc * 4;
        int nb0 = grp * NPT;

        float4 sum[NPT];
        float4 bv = *reinterpret_cast<const float4*>(&sBias[o0]);
#pragma unroll
        for (int k = 0; k < NPT; k++) sum[k] = bv;

#pragma unroll
        for (int r = 0; r < R + 1; r++) {
#pragma unroll
            for (int i4 = 0; i4 < DIN / 4; i4++) {
                const float* wb = &sW[(r * DIN + i4 * 4) * DOUT + o0];
                float4 w0 = *reinterpret_cast<const float4*>(wb);
                float4 w1 = *reinterpret_cast<const float4*>(wb + DOUT);
                float4 w2 = *reinterpret_cast<const float4*>(wb + 2 * DOUT);
                float4 w3 = *reinterpret_cast<const float4*>(wb + 3 * DOUT);
#pragma unroll
                for (int k = 0; k < NPT; k++) {
                    float4 a = *reinterpret_cast<const float4*>(&sAcc[nb0 + k][r][i4 * 4]);
                    sum[k].x += a.x * w0.x + a.y * w1.x + a.z * w2.x + a.w * w3.x;
                    sum[k].y += a.x * w0.y + a.y * w1.y + a.z * w2.y + a.w * w3.y;
                    sum[k].z += a.x * w0.z + a.y * w1.z + a.z * w2.z + a.w * w3.z;
                    sum[k].w += a.x * w0.w + a.y * w1.w + a.z * w2.w + a.w * w3.w;
                }
            }
        }
#pragma unroll
        for (int k = 0; k < NPT; k++) {
            int n = node0 + nb0 + k;
            if (n < N_NODES) {
                float4 sv = sum[k];
                if (RELU) {
                    sv.x = fmaxf(sv.x, 0.f); sv.y = fmaxf(sv.y, 0.f);
                    sv.z = fmaxf(sv.z, 0.f); sv.w = fmaxf(sv.w, 0.f);
                }
                *reinterpret_cast<float4*>(&hout[n * DOUT + o0]) = sv;
            }
        }
    }
}

// ---- strip-reduced max pooling ----
__global__ void pool_kernel(const int* __restrict__ batch) {
    int grp = threadIdx.x / 64;
    int c   = threadIdx.x % 64;
    int n0  = blockIdx.x * 256 + grp * 64;
    if (n0 >= N_NODES) return;
    int nend = min(n0 + 64, N_NODES);
    float cur = __int_as_float(0xff800000);
    int curb  = batch[n0];
    for (int n = n0; n < nend; n++) {
        int   b = batch[n];
        float v = g_h3[n * 64 + c];
        if (b != curb) {
            atomicMax(&g_pool[curb * 64 + c], enc(cur));
            cur = __int_as_float(0xff800000);
            curb = b;
        }
        cur = fmaxf(cur, v);
    }
    atomicMax(&g_pool[curb * 64 + c], enc(cur));
}

// ---- decode + restore pool for next launch ----
__global__ void decode_kernel(float* __restrict__ out) {
    int i = blockIdx.x * blockDim.x + threadIdx.x;
    if (i < NG * 64) {
        unsigned u = g_pool[i];
        out[i] = (u == 0u) ? __int_as_float(0xff800000) : dec(u);
        g_pool[i] = 0u;
    }
}

extern "C" void kernel_launch(void* const* d_in, const int* in_sizes, int n_in,
                              void* d_out, int out_size) {
    const float* x     = (const float*)d_in[0];
    const int*   ei    = (const int*)d_in[1];
    const int*   src   = ei;
    const int*   dst   = ei + N_EDGES;
    const int*   et    = (const int*)d_in[2];
    const int*   batch = (const int*)d_in[3];
    const float* W1 = (const float*)d_in[4];
    const float* r1 = (const float*)d_in[5];
    const float* b1 = (const float*)d_in[6];
    const float* W2 = (const float*)d_in[7];
    const float* r2 = (const float*)d_in[8];
    const float* b2 = (const float*)d_in[9];
    const float* W3 = (const float*)d_in[10];
    const float* r3 = (const float*)d_in[11];
    const float* b3 = (const float*)d_in[12];
    float* out = (float*)d_out;

    float *h1p, *h2p, *h3p;
    cudaGetSymbolAddress((void**)&h1p, g_h1);
    cudaGetSymbolAddress((void**)&h2p, g_h2);
    cudaGetSymbolAddress((void**)&h3p, g_h3);

    const int T = 256;

    count_kernel<<<(N_EDGES + T - 1) / T, T>>>(dst, et);           // 1
    scan_kernel<<<NT2, SCAN_T>>>();                                // 2
    fill_kernel<<<(N_EDGES + T - 1) / T, T>>>(src, dst, et);       // 3

    layer_kernel<16, 16, 64, true ><<<(N_NODES + 63) / 64, T>>>(x,   W1, r1, b1, h1p);  // 4 <- profiled
    layer_kernel<16, 32, 64, true ><<<(N_NODES + 63) / 64, T>>>(h1p, W2, r2, b2, h2p);
    layer_kernel<32, 64, 32, false><<<(N_NODES + 31) / 32, T>>>(h2p, W3, r3, b3, h3p);

    pool_kernel<<<(N_NODES + 255) / 256, T>>>(batch);
    decode_kernel<<<(NG * 64 + T - 1) / T, T>>>(out);
}

// round 6
// speedup vs baseline: 1.1335x; 1.0648x over previous
#include <cuda_runtime.h>

#define N_NODES 100000
#define N_EDGES 1600000
#define R 4
#define NG 256
#define SEG (N_NODES * R)
#define SCAN_T 1024
#define NT2 ((SEG + SCAN_T - 1) / SCAN_T)

typedef unsigned long long u64;

// ---- scratch (zero-init at module load; every launch self-restores) ----
__device__ int      g_cnt[SEG];
__device__ int      g_off[SEG + 1];
__device__ int      g_fill[SEG];
__device__ int      g_esrc[N_EDGES];
__device__ u64      g_state[NT2];
__device__ int      g_ticket;
__device__ float    g_h1[N_NODES * 16];
__device__ float    g_h2[N_NODES * 32];
__device__ unsigned g_pool[NG * 64];

// ---- packed f32x2 helpers ----
__device__ __forceinline__ void fma2(u64& d, u64 a, u64 b, u64 c) {
    asm("fma.rn.f32x2 %0, %1, %2, %3;" : "=l"(d) : "l"(a), "l"(b), "l"(c));
}
__device__ __forceinline__ void add2(u64& d, u64 a, u64 b) {
    asm("add.rn.f32x2 %0, %1, %2;" : "=l"(d) : "l"(a), "l"(b));
}
__device__ __forceinline__ void mul2(u64& d, u64 a, u64 b) {
    asm("mul.rn.f32x2 %0, %1, %2;" : "=l"(d) : "l"(a), "l"(b));
}
__device__ __forceinline__ u64 pack2(float x) {
    u64 d; unsigned u = __float_as_uint(x);
    asm("mov.b64 %0, {%1, %1};" : "=l"(d) : "r"(u));
    return d;
}

__device__ __forceinline__ unsigned enc(float v) {
    unsigned u = __float_as_uint(v);
    return (u & 0x80000000u) ? ~u : (u | 0x80000000u);
}
__device__ __forceinline__ float dec(unsigned u) {
    unsigned bits = (u & 0x80000000u) ? (u ^ 0x80000000u) : ~u;
    return __uint_as_float(bits);
}

// ---- 1. count ----
__global__ void count_kernel(const int* __restrict__ dst,
                             const int* __restrict__ et) {
    int e = blockIdx.x * blockDim.x + threadIdx.x;
    if (e < N_EDGES) atomicAdd(&g_cnt[dst[e] * R + et[e]], 1);
}

// ---- 2. decoupled-lookback scan; seeds off/fill; zeroes cnt ----
__global__ __launch_bounds__(SCAN_T) void scan_kernel() {
    __shared__ int s[SCAN_T];
    __shared__ int s_tile;
    __shared__ int s_prefix;

    if (threadIdx.x == 0) s_tile = atomicAdd(&g_ticket, 1);
    __syncthreads();
    int tile = s_tile;
    int i = tile * SCAN_T + threadIdx.x;
    int v = (i < SEG) ? g_cnt[i] : 0;
    s[threadIdx.x] = v;
    __syncthreads();
    for (int d = 1; d < SCAN_T; d <<= 1) {
        int t = (threadIdx.x >= d) ? s[threadIdx.x - d] : 0;
        __syncthreads();
        s[threadIdx.x] += t;
        __syncthreads();
    }
    int incl  = s[threadIdx.x];
    int total = s[SCAN_T - 1];

    if (threadIdx.x == 0) {
        u64 st = (tile == 0) ? ((2ull << 32) | (unsigned)total)
                             : ((1ull << 32) | (unsigned)total);
        __threadfence();
        atomicExch(&g_state[tile], st);
        if (tile == 0) s_prefix = 0;
    }
    if (tile > 0 && threadIdx.x < 32) {
        int lane = threadIdx.x;
        int j = tile - 1;
        int agg = 0;
        while (true) {
            int idx = j - lane;
            u64 st = (idx >= 0) ? atomicAdd(&g_state[idx], 0ull) : (2ull << 32);
            unsigned flag = (unsigned)(st >> 32);
            unsigned invm = __ballot_sync(0xffffffffu, flag == 0);
            if (invm) continue;
            unsigned prefm = __ballot_sync(0xffffffffu, flag == 2);
            int stop = prefm ? (__ffs(prefm) - 1) : 32;
            int contrib = (lane <= stop) ? (int)(st & 0xffffffffu) : 0;
#pragma unroll
            for (int m = 16; m; m >>= 1) contrib += __shfl_xor_sync(~0u, contrib, m);
            agg += contrib;
            if (stop < 32) break;
            j -= 32;
        }
        if (lane == 0) {
            s_prefix = agg;
            __threadfence();
            atomicExch(&g_state[tile], (2ull << 32) | (unsigned)(agg + total));
        }
    }
    __syncthreads();
    int prefix = s_prefix;
    if (i < SEG) {
        int o = prefix + incl - v;
        g_off[i]  = o;
        g_fill[i] = o;
        g_cnt[i]  = 0;
    }
    if (i == SEG - 1) g_off[SEG] = N_EDGES;
}

// ---- 3. fill CSR; restore scan state ----
__global__ void fill_kernel(const int* __restrict__ src,
                            const int* __restrict__ dst,
                            const int* __restrict__ et) {
    int e = blockIdx.x * blockDim.x + threadIdx.x;
    if (e < N_EDGES) {
        int sg  = dst[e] * R + et[e];
        int pos = atomicAdd(&g_fill[sg], 1);
        g_esrc[pos] = src[e];
    }
    if (e < NT2) g_state[e] = 0ull;
    if (e == 0)  g_ticket = 0;
}

// ============================================================================
// Fused layer with packed f32x2 math.  POOL=true fuses segment-max pooling.
// ============================================================================
template <int DIN, int DOUT, int NB, bool RELU, bool POOL, int MINB>
__global__ __launch_bounds__(256, MINB) void layer_kernel(
        const float* __restrict__ xin,
        const float* __restrict__ W,
        const float* __restrict__ root,
        const float* __restrict__ bias,
        float* __restrict__ hout,
        const int* __restrict__ batch) {
    constexpr int FCH   = DIN / 4;
    constexpr int SLOTS = 32 / FCH;
    constexpr int OC    = DOUT / 4;
    constexpr int NGRP  = 256 / OC;
    constexpr int NPT   = NB / NGRP;
    constexpr int GSLOT = 8;
    static_assert(NB % 8 == 0 && NGRP * NPT == NB, "mapping");

    __shared__ float    sAcc[NB][R + 1][DIN];
    __shared__ float    sW[(R + 1) * DIN * DOUT];
    __shared__ float    sBias[DOUT];
    __shared__ unsigned sPool[POOL ? GSLOT * 64 : 1];
    __shared__ int      sBatch[POOL ? NB : 1];

    for (int i = threadIdx.x; i < R * DIN * DOUT; i += 256) sW[i] = W[i];
    for (int i = threadIdx.x; i < DIN * DOUT; i += 256)
        sW[R * DIN * DOUT + i] = root[i];
    if (threadIdx.x < DOUT) sBias[threadIdx.x] = bias[threadIdx.x];

    const int node0 = blockIdx.x * NB;

    if (POOL) {
        for (int i = threadIdx.x; i < GSLOT * 64; i += 256) sPool[i] = 0u;
        if (threadIdx.x < NB) {
            int n = node0 + threadIdx.x;
            sBatch[threadIdx.x] = (n < N_NODES) ? batch[n] : 0;
        }
    }

    const int wid  = threadIdx.x >> 5;
    const int lane = threadIdx.x & 31;
    const int slot = lane / FCH;
    const int feat = lane % FCH;

    // ---- gather (packed f32x2 masked accumulation) ----
    for (int nn = wid; nn < NB; nn += 8) {
        int n = node0 + nn;
        if (n >= N_NODES) break;
        int sb = n * R;
        int o0 = g_off[sb];
        int b1 = g_off[sb + 1];
        int b2 = g_off[sb + 2];
        int b3 = g_off[sb + 3];
        int e4 = g_off[sb + 4];

        u64 A[R][2];
#pragma unroll
        for (int k = 0; k < R; k++) { A[k][0] = 0ull; A[k][1] = 0ull; }

        for (int p0 = o0; p0 < e4; p0 += SLOTS) {
            int p = p0 + slot;
            if (p < e4) {
                int s = g_esrc[p];
                ulonglong2 v = *reinterpret_cast<const ulonglong2*>(
                                   xin + s * DIN + feat * 4);
                int r = (p >= b1) + (p >= b2) + (p >= b3);
#pragma unroll
                for (int k = 0; k < R; k++) {
                    u64 m = (r == k) ? 0x3f8000003f800000ull : 0ull;
                    fma2(A[k][0], m, v.x, A[k][0]);
                    fma2(A[k][1], m, v.y, A[k][1]);
                }
            }
        }
#pragma unroll
        for (int m = FCH; m < 32; m <<= 1) {
#pragma unroll
            for (int k = 0; k < R; k++) {
                u64 t0 = __shfl_xor_sync(~0u, A[k][0], m);
                u64 t1 = __shfl_xor_sync(~0u, A[k][1], m);
                add2(A[k][0], A[k][0], t0);
                add2(A[k][1], A[k][1], t1);
            }
        }
        if (slot == 0) {
            int c[4] = { b1 - o0, b2 - b1, b3 - b2, e4 - b3 };
#pragma unroll
            for (int k = 0; k < R; k++) {
                u64 iv = pack2(__fdividef(1.f, fmaxf((float)c[k], 1.f)));
                mul2(A[k][0], A[k][0], iv);
                mul2(A[k][1], A[k][1], iv);
                *reinterpret_cast<ulonglong2*>(&sAcc[nn][k][feat * 4]) =
                    make_ulonglong2(A[k][0], A[k][1]);
            }
            *reinterpret_cast<ulonglong2*>(&sAcc[nn][R][feat * 4]) =
                *reinterpret_cast<const ulonglong2*>(xin + n * DIN + feat * 4);
        }
    }
    __syncthreads();

    // ---- transform (packed f32x2) ----
    {
        int oc  = threadIdx.x % OC;
        int grp = threadIdx.x / OC;
        int o0  = oc * 4;
        int nb0 = grp * NPT;

        const u64* bb = reinterpret_cast<const u64*>(&sBias[o0]);
        u64 s01[NPT], s23[NPT];
#pragma unroll
        for (int k = 0; k < NPT; k++) { s01[k] = bb[0]; s23[k] = bb[1]; }

#pragma unroll
        for (int r = 0; r < R + 1; r++) {
#pragma unroll
            for (int i4 = 0; i4 < DIN / 4; i4++) {
                const float* wb = &sW[(r * DIN + i4 * 4) * DOUT + o0];
                ulonglong2 w0 = *reinterpret_cast<const ulonglong2*>(wb);
                ulonglong2 w1 = *reinterpret_cast<const ulonglong2*>(wb + DOUT);
                ulonglong2 w2 = *reinterpret_cast<const ulonglong2*>(wb + 2 * DOUT);
                ulonglong2 w3 = *reinterpret_cast<const ulonglong2*>(wb + 3 * DOUT);
#pragma unroll
                for (int k = 0; k < NPT; k++) {
                    float4 a = *reinterpret_cast<const float4*>(&sAcc[nb0 + k][r][i4 * 4]);
                    u64 aa;
                    aa = pack2(a.x); fma2(s01[k], aa, w0.x, s01[k]); fma2(s23[k], aa, w0.y, s23[k]);
                    aa = pack2(a.y); fma2(s01[k], aa, w1.x, s01[k]); fma2(s23[k], aa, w1.y, s23[k]);
                    aa = pack2(a.z); fma2(s01[k], aa, w2.x, s01[k]); fma2(s23[k], aa, w2.y, s23[k]);
                    aa = pack2(a.w); fma2(s01[k], aa, w3.x, s01[k]); fma2(s23[k], aa, w3.y, s23[k]);
                }
            }
        }
#pragma unroll
        for (int k = 0; k < NPT; k++) {
            int n = node0 + nb0 + k;
            if (n < N_NODES) {
                union { u64 q[2]; float f[4]; } sv;
                sv.q[0] = s01[k]; sv.q[1] = s23[k];
                if (RELU) {
#pragma unroll
                    for (int j = 0; j < 4; j++) sv.f[j] = fmaxf(sv.f[j], 0.f);
                }
                if (!POOL) {
                    *reinterpret_cast<float4*>(&hout[n * DOUT + o0]) =
                        make_float4(sv.f[0], sv.f[1], sv.f[2], sv.f[3]);
                } else {
                    int g  = sBatch[nb0 + k - 0];
                    int gr = g - sBatch[0];
#pragma unroll
                    for (int j = 0; j < 4; j++) {
                        unsigned ev = enc(sv.f[j]);
                        if (gr < GSLOT)
                            atomicMax(&sPool[gr * 64 + o0 + j], ev);
                        else
                            atomicMax(&g_pool[g * 64 + o0 + j], ev);
                    }
                }
            }
        }
    }

    if (POOL) {
        __syncthreads();
        int g0 = sBatch[0];
        for (int i = threadIdx.x; i < GSLOT * 64; i += 256) {
            unsigned v = sPool[i];
            int g = g0 + i / 64;
            if (v != 0u && g < NG)
                atomicMax(&g_pool[g * 64 + (i & 63)], v);
        }
    }
}

// ---- decode + restore pool ----
__global__ void decode_kernel(float* __restrict__ out) {
    int i = blockIdx.x * blockDim.x + threadIdx.x;
    if (i < NG * 64) {
        unsigned u = g_pool[i];
        out[i] = (u == 0u) ? __int_as_float(0xff800000) : dec(u);
        g_pool[i] = 0u;
    }
}

extern "C" void kernel_launch(void* const* d_in, const int* in_sizes, int n_in,
                              void* d_out, int out_size) {
    const float* x     = (const float*)d_in[0];
    const int*   ei    = (const int*)d_in[1];
    const int*   src   = ei;
    const int*   dst   = ei + N_EDGES;
    const int*   et    = (const int*)d_in[2];
    const int*   batch = (const int*)d_in[3];
    const float* W1 = (const float*)d_in[4];
    const float* r1 = (const float*)d_in[5];
    const float* b1 = (const float*)d_in[6];
    const float* W2 = (const float*)d_in[7];
    const float* r2 = (const float*)d_in[8];
    const float* b2 = (const float*)d_in[9];
    const float* W3 = (const float*)d_in[10];
    const float* r3 = (const float*)d_in[11];
    const float* b3 = (const float*)d_in[12];
    float* out = (float*)d_out;

    float *h1p, *h2p;
    cudaGetSymbolAddress((void**)&h1p, g_h1);
    cudaGetSymbolAddress((void**)&h2p, g_h2);

    const int T = 256;

    count_kernel<<<(N_EDGES + T - 1) / T, T>>>(dst, et);         // 1
    scan_kernel<<<NT2, SCAN_T>>>();                              // 2
    fill_kernel<<<(N_EDGES + T - 1) / T, T>>>(src, dst, et);     // 3

    layer_kernel<16, 16, 64, true,  false, 5>                    // 4 <- profiled
        <<<(N_NODES + 63) / 64, T>>>(x,   W1, r1, b1, h1p, nullptr);
    layer_kernel<16, 32, 64, true,  false, 5>
        <<<(N_NODES + 63) / 64, T>>>(h1p, W2, r2, b2, h2p, nullptr);
    layer_kernel<32, 64, 32, false, true,  3>
        <<<(N_NODES + 31) / 32, T>>>(h2p, W3, r3, b3, nullptr, batch);

    decode_kernel<<<(NG * 64 + T - 1) / T, T>>>(out);
}

// round 7
// speedup vs baseline: 1.2555x; 1.1076x over previous
#include <cuda_runtime.h>

#define N_NODES 100000
#define N_EDGES 1600000
#define R 4
#define NG 256
#define SEG (N_NODES * R)
#define SCAN_T 1024
#define NT2 ((SEG + SCAN_T - 1) / SCAN_T)

typedef unsigned long long u64;

// ---- scratch (zero-init at module load; launches self-restore) ----
__device__ int      g_cnt[SEG];
__device__ int      g_off[SEG + 1];
__device__ int      g_fill[SEG];
__device__ float    g_inv[SEG];
__device__ int      g_esrc[N_EDGES];
__device__ u64      g_state[NT2];
__device__ int      g_ticket;
__device__ float    g_h1[N_NODES * 16];
__device__ float    g_h2[N_NODES * 32];
__device__ unsigned g_pool[NG * 64];

// ---- packed f32x2 helpers ----
__device__ __forceinline__ void fma2(u64& d, u64 a, u64 b, u64 c) {
    asm("fma.rn.f32x2 %0, %1, %2, %3;" : "=l"(d) : "l"(a), "l"(b), "l"(c));
}
__device__ __forceinline__ void add2(u64& d, u64 a, u64 b) {
    asm("add.rn.f32x2 %0, %1, %2;" : "=l"(d) : "l"(a), "l"(b));
}
__device__ __forceinline__ void mul2(u64& d, u64 a, u64 b) {
    asm("mul.rn.f32x2 %0, %1, %2;" : "=l"(d) : "l"(a), "l"(b));
}
__device__ __forceinline__ u64 pack2(float x) {
    u64 d; unsigned u = __float_as_uint(x);
    asm("mov.b64 %0, {%1, %1};" : "=l"(d) : "r"(u));
    return d;
}

__device__ __forceinline__ unsigned enc(float v) {
    unsigned u = __float_as_uint(v);
    return (u & 0x80000000u) ? ~u : (u | 0x80000000u);
}
__device__ __forceinline__ float dec(unsigned u) {
    unsigned bits = (u & 0x80000000u) ? (u ^ 0x80000000u) : ~u;
    return __uint_as_float(bits);
}

// ---- 1. count ----
__global__ void count_kernel(const int* __restrict__ dst,
                             const int* __restrict__ et) {
    int e = blockIdx.x * blockDim.x + threadIdx.x;
    if (e < N_EDGES) atomicAdd(&g_cnt[dst[e] * R + et[e]], 1);
}

// ---- 2. decoupled-lookback scan; seeds off/fill/inv; zeroes cnt ----
__global__ __launch_bounds__(SCAN_T) void scan_kernel() {
    __shared__ int s[SCAN_T];
    __shared__ int s_tile;
    __shared__ int s_prefix;

    if (threadIdx.x == 0) s_tile = atomicAdd(&g_ticket, 1);
    __syncthreads();
    int tile = s_tile;
    int i = tile * SCAN_T + threadIdx.x;
    int v = (i < SEG) ? g_cnt[i] : 0;
    s[threadIdx.x] = v;
    __syncthreads();
    for (int d = 1; d < SCAN_T; d <<= 1) {
        int t = (threadIdx.x >= d) ? s[threadIdx.x - d] : 0;
        __syncthreads();
        s[threadIdx.x] += t;
        __syncthreads();
    }
    int incl  = s[threadIdx.x];
    int total = s[SCAN_T - 1];

    if (threadIdx.x == 0) {
        u64 st = (tile == 0) ? ((2ull << 32) | (unsigned)total)
                             : ((1ull << 32) | (unsigned)total);
        __threadfence();
        atomicExch(&g_state[tile], st);
        if (tile == 0) s_prefix = 0;
    }
    if (tile > 0 && threadIdx.x < 32) {
        int lane = threadIdx.x;
        int j = tile - 1;
        int agg = 0;
        while (true) {
            int idx = j - lane;
            u64 st = (idx >= 0) ? atomicAdd(&g_state[idx], 0ull) : (2ull << 32);
            unsigned flag = (unsigned)(st >> 32);
            unsigned invm = __ballot_sync(0xffffffffu, flag == 0);
            if (invm) continue;
            unsigned prefm = __ballot_sync(0xffffffffu, flag == 2);
            int stop = prefm ? (__ffs(prefm) - 1) : 32;
            int contrib = (lane <= stop) ? (int)(st & 0xffffffffu) : 0;
#pragma unroll
            for (int m = 16; m; m >>= 1) contrib += __shfl_xor_sync(~0u, contrib, m);
            agg += contrib;
            if (stop < 32) break;
            j -= 32;
        }
        if (lane == 0) {
            s_prefix = agg;
            __threadfence();
            atomicExch(&g_state[tile], (2ull << 32) | (unsigned)(agg + total));
        }
    }
    __syncthreads();
    int prefix = s_prefix;
    if (i < SEG) {
        int o = prefix + incl - v;
        g_off[i]  = o;
        g_fill[i] = o;
        g_inv[i]  = __fdividef(1.f, fmaxf((float)v, 1.f));
        g_cnt[i]  = 0;
    }
    if (i == SEG - 1) g_off[SEG] = N_EDGES;
}

// ---- 3. fill CSR; restore scan state ----
__global__ void fill_kernel(const int* __restrict__ src,
                            const int* __restrict__ dst,
                            const int* __restrict__ et) {
    int e = blockIdx.x * blockDim.x + threadIdx.x;
    if (e < N_EDGES) {
        int sg  = dst[e] * R + et[e];
        int pos = atomicAdd(&g_fill[sg], 1);
        g_esrc[pos] = src[e];
    }
    if (e < NT2) g_state[e] = 0ull;
    if (e == 0)  g_ticket = 0;
}

// ============================================================================
// Fused layer: relation-partitioned gather (4 groups x 8 lanes; no masks,
// no reduction) + packed-f32x2 transform.  POOL fuses segment-max pooling.
// ============================================================================
template <int DIN, int DOUT, int NB, bool RELU, bool POOL, int MINB>
__global__ __launch_bounds__(256, MINB) void layer_kernel(
        const float* __restrict__ xin,
        const float* __restrict__ W,
        const float* __restrict__ root,
        const float* __restrict__ bias,
        float* __restrict__ hout,
        const int* __restrict__ batch) {
    constexpr int F     = DIN / 8;            // floats per lane (2 or 4)
    constexpr int NU    = F / 2;              // u64 per lane (1 or 2)
    constexpr int OC    = DOUT / 4;
    constexpr int NGRP  = 256 / OC;
    constexpr int NPT   = NB / NGRP;
    constexpr int GSLOT = 8;
    static_assert(NB % 8 == 0 && NGRP * NPT == NB, "mapping");
    static_assert(F == 2 || F == 4, "lane feature width");

    __shared__ float    sAcc[NB][R + 1][DIN];
    __shared__ float    sW[(R + 1) * DIN * DOUT];
    __shared__ float    sBias[DOUT];
    __shared__ unsigned sPool[POOL ? GSLOT * 64 : 1];
    __shared__ int      sBatch[POOL ? NB : 1];

    for (int i = threadIdx.x; i < R * DIN * DOUT; i += 256) sW[i] = W[i];
    for (int i = threadIdx.x; i < DIN * DOUT; i += 256)
        sW[R * DIN * DOUT + i] = root[i];
    if (threadIdx.x < DOUT) sBias[threadIdx.x] = bias[threadIdx.x];

    const int node0 = blockIdx.x * NB;

    if (POOL) {
        for (int i = threadIdx.x; i < GSLOT * 64; i += 256) sPool[i] = 0u;
        if (threadIdx.x < NB) {
            int n = node0 + threadIdx.x;
            sBatch[threadIdx.x] = (n < N_NODES) ? batch[n] : 0;
        }
    }

    const int wid   = threadIdx.x >> 5;
    const int lane  = threadIdx.x & 31;
    const int group = lane >> 3;              // relation 0..3
    const int fl    = lane & 7;               // feature sub-index

    // ---- gather: warp per node; group k walks segment (n,k) serially ----
    for (int nn = wid; nn < NB; nn += 8) {
        int n = node0 + nn;
        if (n >= N_NODES) break;
        int sb = n * R + group;
        int o  = g_off[sb];
        int e  = g_off[sb + 1];

        u64 acc[NU];
#pragma unroll
        for (int q = 0; q < NU; q++) acc[q] = 0ull;

        for (int p = o; p < e; p++) {
            int s = g_esrc[p];
            if (F == 2) {
                u64 v = *reinterpret_cast<const u64*>(xin + s * DIN + fl * 2);
                add2(acc[0], acc[0], v);
            } else {
                ulonglong2 v = *reinterpret_cast<const ulonglong2*>(
                                   xin + s * DIN + fl * 4);
                add2(acc[0], acc[0], v.x);
                add2(acc[1], acc[1], v.y);
            }
        }
        u64 iv = pack2(g_inv[sb]);
#pragma unroll
        for (int q = 0; q < NU; q++) mul2(acc[q], acc[q], iv);

        if (F == 2) {
            *reinterpret_cast<u64*>(&sAcc[nn][group][fl * 2]) = acc[0];
            if (group == 0)
                *reinterpret_cast<u64*>(&sAcc[nn][R][fl * 2]) =
                    *reinterpret_cast<const u64*>(xin + n * DIN + fl * 2);
        } else {
            *reinterpret_cast<ulonglong2*>(&sAcc[nn][group][fl * 4]) =
                make_ulonglong2(acc[0], acc[1]);
            if (group == 0)
                *reinterpret_cast<ulonglong2*>(&sAcc[nn][R][fl * 4]) =
                    *reinterpret_cast<const ulonglong2*>(xin + n * DIN + fl * 4);
        }
    }
    __syncthreads();

    // ---- transform (packed f32x2) ----
    {
        int oc  = threadIdx.x % OC;
        int grp = threadIdx.x / OC;
        int o0  = oc * 4;
        int nb0 = grp * NPT;

        const u64* bb = reinterpret_cast<const u64*>(&sBias[o0]);
        u64 s01[NPT], s23[NPT];
#pragma unroll
        for (int k = 0; k < NPT; k++) { s01[k] = bb[0]; s23[k] = bb[1]; }

#pragma unroll
        for (int r = 0; r < R + 1; r++) {
#pragma unroll
            for (int i4 = 0; i4 < DIN / 4; i4++) {
                const float* wb = &sW[(r * DIN + i4 * 4) * DOUT + o0];
                ulonglong2 w0 = *reinterpret_cast<const ulonglong2*>(wb);
                ulonglong2 w1 = *reinterpret_cast<const ulonglong2*>(wb + DOUT);
                ulonglong2 w2 = *reinterpret_cast<const ulonglong2*>(wb + 2 * DOUT);
                ulonglong2 w3 = *reinterpret_cast<const ulonglong2*>(wb + 3 * DOUT);
#pragma unroll
                for (int k = 0; k < NPT; k++) {
                    float4 a = *reinterpret_cast<const float4*>(&sAcc[nb0 + k][r][i4 * 4]);
                    u64 aa;
                    aa = pack2(a.x); fma2(s01[k], aa, w0.x, s01[k]); fma2(s23[k], aa, w0.y, s23[k]);
                    aa = pack2(a.y); fma2(s01[k], aa, w1.x, s01[k]); fma2(s23[k], aa, w1.y, s23[k]);
                    aa = pack2(a.z); fma2(s01[k], aa, w2.x, s01[k]); fma2(s23[k], aa, w2.y, s23[k]);
                    aa = pack2(a.w); fma2(s01[k], aa, w3.x, s01[k]); fma2(s23[k], aa, w3.y, s23[k]);
                }
            }
        }
#pragma unroll
        for (int k = 0; k < NPT; k++) {
            int n = node0 + nb0 + k;
            if (n < N_NODES) {
                union { u64 q[2]; float f[4]; } sv;
                sv.q[0] = s01[k]; sv.q[1] = s23[k];
                if (RELU) {
#pragma unroll
                    for (int j = 0; j < 4; j++) sv.f[j] = fmaxf(sv.f[j], 0.f);
                }
                if (!POOL) {
                    *reinterpret_cast<float4*>(&hout[n * DOUT + o0]) =
                        make_float4(sv.f[0], sv.f[1], sv.f[2], sv.f[3]);
                } else {
                    int g  = sBatch[nb0 + k];
                    int gr = g - sBatch[0];
#pragma unroll
                    for (int j = 0; j < 4; j++) {
                        unsigned ev = enc(sv.f[j]);
                        if (gr < GSLOT)
                            atomicMax(&sPool[gr * 64 + o0 + j], ev);
                        else
                            atomicMax(&g_pool[g * 64 + o0 + j], ev);
                    }
                }
            }
        }
    }

    if (POOL) {
        __syncthreads();
        int g0 = sBatch[0];
        for (int i = threadIdx.x; i < GSLOT * 64; i += 256) {
            unsigned v = sPool[i];
            int g = g0 + i / 64;
            if (v != 0u && g < NG)
                atomicMax(&g_pool[g * 64 + (i & 63)], v);
        }
    }
}

// ---- decode + restore pool ----
__global__ void decode_kernel(float* __restrict__ out) {
    int i = blockIdx.x * blockDim.x + threadIdx.x;
    if (i < NG * 64) {
        unsigned u = g_pool[i];
        out[i] = (u == 0u) ? __int_as_float(0xff800000) : dec(u);
        g_pool[i] = 0u;
    }
}

extern "C" void kernel_launch(void* const* d_in, const int* in_sizes, int n_in,
                              void* d_out, int out_size) {
    const float* x     = (const float*)d_in[0];
    const int*   ei    = (const int*)d_in[1];
    const int*   src   = ei;
    const int*   dst   = ei + N_EDGES;
    const int*   et    = (const int*)d_in[2];
    const int*   batch = (const int*)d_in[3];
    const float* W1 = (const float*)d_in[4];
    const float* r1 = (const float*)d_in[5];
    const float* b1 = (const float*)d_in[6];
    const float* W2 = (const float*)d_in[7];
    const float* r2 = (const float*)d_in[8];
    const float* b2 = (const float*)d_in[9];
    const float* W3 = (const float*)d_in[10];
    const float* r3 = (const float*)d_in[11];
    const float* b3 = (const float*)d_in[12];
    float* out = (float*)d_out;

    float *h1p, *h2p;
    cudaGetSymbolAddress((void**)&h1p, g_h1);
    cudaGetSymbolAddress((void**)&h2p, g_h2);

    const int T = 256;

    count_kernel<<<(N_EDGES + T - 1) / T, T>>>(dst, et);         // 1
    scan_kernel<<<NT2, SCAN_T>>>();                              // 2
    fill_kernel<<<(N_EDGES + T - 1) / T, T>>>(src, dst, et);     // 3

    layer_kernel<16, 16, 64, true,  false, 5>                    // 4 <- profiled
        <<<(N_NODES + 63) / 64, T>>>(x,   W1, r1, b1, h1p, nullptr);
    layer_kernel<16, 32, 64, true,  false, 5>
        <<<(N_NODES + 63) / 64, T>>>(h1p, W2, r2, b2, h2p, nullptr);
    layer_kernel<32, 64, 32, false, true,  3>
        <<<(N_NODES + 31) / 32, T>>>(h2p, W3, r3, b3, nullptr, batch);

    decode_kernel<<<(NG * 64 + T - 1) / T, T>>>(out);
}

// round 8
// speedup vs baseline: 1.2769x; 1.0170x over previous
#include <cuda_runtime.h>

#define N_NODES 100000
#define N_EDGES 1600000
#define R 4
#define NG 256
#define SEG (N_NODES * R)
#define SCAN_T 1024
#define NT2 ((SEG + SCAN_T - 1) / SCAN_T)

typedef unsigned long long u64;

// ---- scratch (zero-init at module load; launches self-restore) ----
__device__ int      g_cnt[SEG];
__device__ int      g_off[SEG + 1];
__device__ int      g_fill[SEG];
__device__ float    g_inv[SEG];
__device__ int      g_esrc[N_EDGES];
__device__ u64      g_state[NT2];
__device__ int      g_ticket;
__device__ float    g_h1[N_NODES * 16];
__device__ float    g_h2[N_NODES * 32];
__device__ unsigned g_pool[NG * 64];

// ---- packed f32x2 helpers ----
__device__ __forceinline__ void fma2(u64& d, u64 a, u64 b, u64 c) {
    asm("fma.rn.f32x2 %0, %1, %2, %3;" : "=l"(d) : "l"(a), "l"(b), "l"(c));
}
__device__ __forceinline__ void add2(u64& d, u64 a, u64 b) {
    asm("add.rn.f32x2 %0, %1, %2;" : "=l"(d) : "l"(a), "l"(b));
}
__device__ __forceinline__ void mul2(u64& d, u64 a, u64 b) {
    asm("mul.rn.f32x2 %0, %1, %2;" : "=l"(d) : "l"(a), "l"(b));
}
__device__ __forceinline__ u64 pack2(float x) {
    u64 d; unsigned u = __float_as_uint(x);
    asm("mov.b64 %0, {%1, %1};" : "=l"(d) : "r"(u));
    return d;
}

__device__ __forceinline__ unsigned enc(float v) {
    unsigned u = __float_as_uint(v);
    return (u & 0x80000000u) ? ~u : (u | 0x80000000u);
}
__device__ __forceinline__ float dec(unsigned u) {
    unsigned bits = (u & 0x80000000u) ? (u ^ 0x80000000u) : ~u;
    return __uint_as_float(bits);
}

// ---- 1. count ----
__global__ void count_kernel(const int* __restrict__ dst,
                             const int* __restrict__ et) {
    int e = blockIdx.x * blockDim.x + threadIdx.x;
    if (e < N_EDGES) atomicAdd(&g_cnt[dst[e] * R + et[e]], 1);
}

// ---- 2. decoupled-lookback scan; seeds off/fill/inv; zeroes cnt ----
__global__ __launch_bounds__(SCAN_T) void scan_kernel() {
    __shared__ int s[SCAN_T];
    __shared__ int s_tile;
    __shared__ int s_prefix;

    if (threadIdx.x == 0) s_tile = atomicAdd(&g_ticket, 1);
    __syncthreads();
    int tile = s_tile;
    int i = tile * SCAN_T + threadIdx.x;
    int v = (i < SEG) ? g_cnt[i] : 0;
    s[threadIdx.x] = v;
    __syncthreads();
    for (int d = 1; d < SCAN_T; d <<= 1) {
        int t = (threadIdx.x >= d) ? s[threadIdx.x - d] : 0;
        __syncthreads();
        s[threadIdx.x] += t;
        __syncthreads();
    }
    int incl  = s[threadIdx.x];
    int total = s[SCAN_T - 1];

    if (threadIdx.x == 0) {
        u64 st = (tile == 0) ? ((2ull << 32) | (unsigned)total)
                             : ((1ull << 32) | (unsigned)total);
        __threadfence();
        atomicExch(&g_state[tile], st);
        if (tile == 0) s_prefix = 0;
    }
    if (tile > 0 && threadIdx.x < 32) {
        int lane = threadIdx.x;
        int j = tile - 1;
        int agg = 0;
        while (true) {
            int idx = j - lane;
            u64 st = (idx >= 0) ? atomicAdd(&g_state[idx], 0ull) : (2ull << 32);
            unsigned flag = (unsigned)(st >> 32);
            unsigned invm = __ballot_sync(0xffffffffu, flag == 0);
            if (invm) continue;
            unsigned prefm = __ballot_sync(0xffffffffu, flag == 2);
            int stop = prefm ? (__ffs(prefm) - 1) : 32;
            int contrib = (lane <= stop) ? (int)(st & 0xffffffffu) : 0;
#pragma unroll
            for (int m = 16; m; m >>= 1) contrib += __shfl_xor_sync(~0u, contrib, m);
            agg += contrib;
            if (stop < 32) break;
            j -= 32;
        }
        if (lane == 0) {
            s_prefix = agg;
            __threadfence();
            atomicExch(&g_state[tile], (2ull << 32) | (unsigned)(agg + total));
        }
    }
    __syncthreads();
    int prefix = s_prefix;
    if (i < SEG) {
        int o = prefix + incl - v;
        g_off[i]  = o;
        g_fill[i] = o;
        g_inv[i]  = __fdividef(1.f, fmaxf((float)v, 1.f));
        g_cnt[i]  = 0;
    }
    if (i == SEG - 1) g_off[SEG] = N_EDGES;
}

// ---- 3. fill CSR; restore scan state ----
__global__ void fill_kernel(const int* __restrict__ src,
                            const int* __restrict__ dst,
                            const int* __restrict__ et) {
    int e = blockIdx.x * blockDim.x + threadIdx.x;
    if (e < N_EDGES) {
        int sg  = dst[e] * R + et[e];
        int pos = atomicAdd(&g_fill[sg], 1);
        g_esrc[pos] = src[e];
    }
    if (e < NT2) g_state[e] = 0ull;
    if (e == 0)  g_ticket = 0;
}

// ============================================================================
// Fused layer: relation-partitioned, software-pipelined gather (unroll-4,
// dual accumulators -> MLP=4) + packed-f32x2 transform.  POOL fuses pooling.
// ============================================================================
template <int DIN, int DOUT, int NB, bool RELU, bool POOL, int MINB>
__global__ __launch_bounds__(256, MINB) void layer_kernel(
        const float* __restrict__ xin,
        const float* __restrict__ W,
        const float* __restrict__ root,
        const float* __restrict__ bias,
        float* __restrict__ hout,
        const int* __restrict__ batch) {
    constexpr int F     = DIN / 8;            // floats per lane (2 or 4)
    constexpr int NU    = F / 2;              // u64 per lane (1 or 2)
    constexpr int OC    = DOUT / 4;
    constexpr int NGRP  = 256 / OC;
    constexpr int NPT   = NB / NGRP;
    constexpr int GSLOT = 8;
    static_assert(NB % 8 == 0 && NGRP * NPT == NB, "mapping");
    static_assert(F == 2 || F == 4, "lane feature width");

    __shared__ float    sAcc[NB][R + 1][DIN];
    __shared__ float    sW[(R + 1) * DIN * DOUT];
    __shared__ float    sBias[DOUT];
    __shared__ unsigned sPool[POOL ? GSLOT * 64 : 1];
    __shared__ int      sBatch[POOL ? NB : 1];

    for (int i = threadIdx.x; i < R * DIN * DOUT; i += 256) sW[i] = W[i];
    for (int i = threadIdx.x; i < DIN * DOUT; i += 256)
        sW[R * DIN * DOUT + i] = root[i];
    if (threadIdx.x < DOUT) sBias[threadIdx.x] = bias[threadIdx.x];

    const int node0 = blockIdx.x * NB;

    if (POOL) {
        for (int i = threadIdx.x; i < GSLOT * 64; i += 256) sPool[i] = 0u;
        if (threadIdx.x < NB) {
            int n = node0 + threadIdx.x;
            sBatch[threadIdx.x] = (n < N_NODES) ? batch[n] : 0;
        }
    }

    const int wid   = threadIdx.x >> 5;
    const int lane  = threadIdx.x & 31;
    const int group = lane >> 3;              // relation 0..3
    const int fl    = lane & 7;               // feature sub-index

    // ---- gather: group k walks segment (n,k); 4-deep pipelined loads ----
    for (int nn = wid; nn < NB; nn += 8) {
        int n = node0 + nn;
        if (n >= N_NODES) break;
        int sb = n * R + group;
        int o  = g_off[sb];
        int e  = g_off[sb + 1];

        u64 acc0[NU], acc1[NU];
#pragma unroll
        for (int q = 0; q < NU; q++) { acc0[q] = 0ull; acc1[q] = 0ull; }

        int p = o;
        for (; p + 4 <= e; p += 4) {
            int s0 = g_esrc[p + 0];
            int s1 = g_esrc[p + 1];
            int s2 = g_esrc[p + 2];
            int s3 = g_esrc[p + 3];
            if (F == 2) {
                u64 v0 = *reinterpret_cast<const u64*>(xin + s0 * DIN + fl * 2);
                u64 v1 = *reinterpret_cast<const u64*>(xin + s1 * DIN + fl * 2);
                u64 v2 = *reinterpret_cast<const u64*>(xin + s2 * DIN + fl * 2);
                u64 v3 = *reinterpret_cast<const u64*>(xin + s3 * DIN + fl * 2);
                add2(acc0[0], acc0[0], v0);
                add2(acc1[0], acc1[0], v1);
                add2(acc0[0], acc0[0], v2);
                add2(acc1[0], acc1[0], v3);
            } else {
                ulonglong2 v0 = *reinterpret_cast<const ulonglong2*>(xin + s0 * DIN + fl * 4);
                ulonglong2 v1 = *reinterpret_cast<const ulonglong2*>(xin + s1 * DIN + fl * 4);
                ulonglong2 v2 = *reinterpret_cast<const ulonglong2*>(xin + s2 * DIN + fl * 4);
                ulonglong2 v3 = *reinterpret_cast<const ulonglong2*>(xin + s3 * DIN + fl * 4);
                add2(acc0[0], acc0[0], v0.x); add2(acc0[1], acc0[1], v0.y);
                add2(acc1[0], acc1[0], v1.x); add2(acc1[1], acc1[1], v1.y);
                add2(acc0[0], acc0[0], v2.x); add2(acc0[1], acc0[1], v2.y);
                add2(acc1[0], acc1[0], v3.x); add2(acc1[1], acc1[1], v3.y);
            }
        }
        // tail (<=3 edges): issue loads before accumulating
        {
            int rem = e - p;
            int t0 = (rem > 0) ? g_esrc[p + 0] : 0;
            int t1 = (rem > 1) ? g_esrc[p + 1] : 0;
            int t2 = (rem > 2) ? g_esrc[p + 2] : 0;
            if (F == 2) {
                u64 v0 = (rem > 0) ? *reinterpret_cast<const u64*>(xin + t0 * DIN + fl * 2) : 0ull;
                u64 v1 = (rem > 1) ? *reinterpret_cast<const u64*>(xin + t1 * DIN + fl * 2) : 0ull;
                u64 v2 = (rem > 2) ? *reinterpret_cast<const u64*>(xin + t2 * DIN + fl * 2) : 0ull;
                add2(acc0[0], acc0[0], v0);
                add2(acc1[0], acc1[0], v1);
                add2(acc0[0], acc0[0], v2);
            } else {
                ulonglong2 z = make_ulonglong2(0ull, 0ull);
                ulonglong2 v0 = (rem > 0) ? *reinterpret_cast<const ulonglong2*>(xin + t0 * DIN + fl * 4) : z;
                ulonglong2 v1 = (rem > 1) ? *reinterpret_cast<const ulonglong2*>(xin + t1 * DIN + fl * 4) : z;
                ulonglong2 v2 = (rem > 2) ? *reinterpret_cast<const ulonglong2*>(xin + t2 * DIN + fl * 4) : z;
                add2(acc0[0], acc0[0], v0.x); add2(acc0[1], acc0[1], v0.y);
                add2(acc1[0], acc1[0], v1.x); add2(acc1[1], acc1[1], v1.y);
                add2(acc0[0], acc0[0], v2.x); add2(acc0[1], acc0[1], v2.y);
            }
        }

        u64 iv = pack2(g_inv[sb]);
#pragma unroll
        for (int q = 0; q < NU; q++) {
            add2(acc0[q], acc0[q], acc1[q]);
            mul2(acc0[q], acc0[q], iv);
        }

        if (F == 2) {
            *reinterpret_cast<u64*>(&sAcc[nn][group][fl * 2]) = acc0[0];
            if (group == 0)
                *reinterpret_cast<u64*>(&sAcc[nn][R][fl * 2]) =
                    *reinterpret_cast<const u64*>(xin + n * DIN + fl * 2);
        } else {
            *reinterpret_cast<ulonglong2*>(&sAcc[nn][group][fl * 4]) =
                make_ulonglong2(acc0[0], acc0[1]);
            if (group == 0)
                *reinterpret_cast<ulonglong2*>(&sAcc[nn][R][fl * 4]) =
                    *reinterpret_cast<const ulonglong2*>(xin + n * DIN + fl * 4);
        }
    }
    __syncthreads();

    // ---- transform (packed f32x2) ----
    {
        int oc  = threadIdx.x % OC;
        int grp = threadIdx.x / OC;
        int o0  = oc * 4;
        int nb0 = grp * NPT;

        const u64* bb = reinterpret_cast<const u64*>(&sBias[o0]);
        u64 s01[NPT], s23[NPT];
#pragma unroll
        for (int k = 0; k < NPT; k++) { s01[k] = bb[0]; s23[k] = bb[1]; }

#pragma unroll
        for (int r = 0; r < R + 1; r++) {
#pragma unroll
            for (int i4 = 0; i4 < DIN / 4; i4++) {
                const float* wb = &sW[(r * DIN + i4 * 4) * DOUT + o0];
                ulonglong2 w0 = *reinterpret_cast<const ulonglong2*>(wb);
                ulonglong2 w1 = *reinterpret_cast<const ulonglong2*>(wb + DOUT);
                ulonglong2 w2 = *reinterpret_cast<const ulonglong2*>(wb + 2 * DOUT);
                ulonglong2 w3 = *reinterpret_cast<const ulonglong2*>(wb + 3 * DOUT);
#pragma unroll
                for (int k = 0; k < NPT; k++) {
                    float4 a = *reinterpret_cast<const float4*>(&sAcc[nb0 + k][r][i4 * 4]);
                    u64 aa;
                    aa = pack2(a.x); fma2(s01[k], aa, w0.x, s01[k]); fma2(s23[k], aa, w0.y, s23[k]);
                    aa = pack2(a.y); fma2(s01[k], aa, w1.x, s01[k]); fma2(s23[k], aa, w1.y, s23[k]);
                    aa = pack2(a.z); fma2(s01[k], aa, w2.x, s01[k]); fma2(s23[k], aa, w2.y, s23[k]);
                    aa = pack2(a.w); fma2(s01[k], aa, w3.x, s01[k]); fma2(s23[k], aa, w3.y, s23[k]);
                }
            }
        }
#pragma unroll
        for (int k = 0; k < NPT; k++) {
            int n = node0 + nb0 + k;
            if (n < N_NODES) {
                union { u64 q[2]; float f[4]; } sv;
                sv.q[0] = s01[k]; sv.q[1] = s23[k];
                if (RELU) {
#pragma unroll
                    for (int j = 0; j < 4; j++) sv.f[j] = fmaxf(sv.f[j], 0.f);
                }
                if (!POOL) {
                    *reinterpret_cast<float4*>(&hout[n * DOUT + o0]) =
                        make_float4(sv.f[0], sv.f[1], sv.f[2], sv.f[3]);
                } else {
                    int g  = sBatch[nb0 + k];
                    int gr = g - sBatch[0];
#pragma unroll
                    for (int j = 0; j < 4; j++) {
                        unsigned ev = enc(sv.f[j]);
                        if (gr < GSLOT)
                            atomicMax(&sPool[gr * 64 + o0 + j], ev);
                        else
                            atomicMax(&g_pool[g * 64 + o0 + j], ev);
                    }
                }
            }
        }
    }

    if (POOL) {
        __syncthreads();
        int g0 = sBatch[0];
        for (int i = threadIdx.x; i < GSLOT * 64; i += 256) {
            unsigned v = sPool[i];
            int g = g0 + i / 64;
            if (v != 0u && g < NG)
                atomicMax(&g_pool[g * 64 + (i & 63)], v);
        }
    }
}

// ---- decode + restore pool ----
__global__ void decode_kernel(float* __restrict__ out) {
    int i = blockIdx.x * blockDim.x + threadIdx.x;
    if (i < NG * 64) {
        unsigned u = g_pool[i];
        out[i] = (u == 0u) ? __int_as_float(0xff800000) : dec(u);
        g_pool[i] = 0u;
    }
}

extern "C" void kernel_launch(void* const* d_in, const int* in_sizes, int n_in,
                              void* d_out, int out_size) {
    const float* x     = (const float*)d_in[0];
    const int*   ei    = (const int*)d_in[1];
    const int*   src   = ei;
    const int*   dst   = ei + N_EDGES;
    const int*   et    = (const int*)d_in[2];
    const int*   batch = (const int*)d_in[3];
    const float* W1 = (const float*)d_in[4];
    const float* r1 = (const float*)d_in[5];
    const float* b1 = (const float*)d_in[6];
    const float* W2 = (const float*)d_in[7];
    const float* r2 = (const float*)d_in[8];
    const float* b2 = (const float*)d_in[9];
    const float* W3 = (const float*)d_in[10];
    const float* r3 = (const float*)d_in[11];
    const float* b3 = (const float*)d_in[12];
    float* out = (float*)d_out;

    float *h1p, *h2p;
    cudaGetSymbolAddress((void**)&h1p, g_h1);
    cudaGetSymbolAddress((void**)&h2p, g_h2);

    const int T = 256;

    count_kernel<<<(N_EDGES + T - 1) / T, T>>>(dst, et);         // 1
    scan_kernel<<<NT2, SCAN_T>>>();                              // 2
    fill_kernel<<<(N_EDGES + T - 1) / T, T>>>(src, dst, et);     // 3

    layer_kernel<16, 16, 64, true,  false, 5>                    // 4 <- profiled
        <<<(N_NODES + 63) / 64, T>>>(x,   W1, r1, b1, h1p, nullptr);
    layer_kernel<16, 32, 64, true,  false, 5>
        <<<(N_NODES + 63) / 64, T>>>(h1p, W2, r2, b2, h2p, nullptr);
    layer_kernel<32, 64, 32, false, true,  3>
        <<<(N_NODES + 31) / 32, T>>>(h2p, W3, r3, b3, nullptr, batch);

    decode_kernel<<<(NG * 64 + T - 1) / T, T>>>(out);
}

// round 9
// speedup vs baseline: 1.4185x; 1.1110x over previous
#include <cuda_runtime.h>

#define N_NODES 100000
#define N_EDGES 1600000
#define R 4
#define NG 256
#define SEG (N_NODES * R)
#define SCAN_T 1024
#define NT2 ((SEG + SCAN_T - 1) / SCAN_T)

typedef unsigned long long u64;

// ---- scratch (zero-init at module load; launches self-restore) ----
__device__ int      g_cnt[SEG];
__device__ int      g_off[SEG + 1];
__device__ int      g_fill[SEG];
__device__ float    g_inv[SEG];
__device__ int      g_esrc[N_EDGES];
__device__ u64      g_state[NT2];
__device__ int      g_ticket;
__device__ float    g_h1[N_NODES * 16];
__device__ float    g_h2[N_NODES * 32];
__device__ unsigned g_pool[NG * 64];

// ---- packed f32x2 helpers ----
__device__ __forceinline__ void fma2(u64& d, u64 a, u64 b, u64 c) {
    asm("fma.rn.f32x2 %0, %1, %2, %3;" : "=l"(d) : "l"(a), "l"(b), "l"(c));
}
__device__ __forceinline__ void add2(u64& d, u64 a, u64 b) {
    asm("add.rn.f32x2 %0, %1, %2;" : "=l"(d) : "l"(a), "l"(b));
}
__device__ __forceinline__ void mul2(u64& d, u64 a, u64 b) {
    asm("mul.rn.f32x2 %0, %1, %2;" : "=l"(d) : "l"(a), "l"(b));
}
__device__ __forceinline__ u64 pack2(float x) {
    u64 d; unsigned u = __float_as_uint(x);
    asm("mov.b64 %0, {%1, %1};" : "=l"(d) : "r"(u));
    return d;
}

__device__ __forceinline__ unsigned enc(float v) {
    unsigned u = __float_as_uint(v);
    return (u & 0x80000000u) ? ~u : (u | 0x80000000u);
}
__device__ __forceinline__ float dec(unsigned u) {
    unsigned bits = (u & 0x80000000u) ? (u ^ 0x80000000u) : ~u;
    return __uint_as_float(bits);
}

// ---- 1. count ----
__global__ void count_kernel(const int* __restrict__ dst,
                             const int* __restrict__ et) {
    int e = blockIdx.x * blockDim.x + threadIdx.x;
    if (e < N_EDGES) atomicAdd(&g_cnt[dst[e] * R + et[e]], 1);
}

// ---- 2. decoupled-lookback scan; seeds off/fill/inv; zeroes cnt ----
__global__ __launch_bounds__(SCAN_T) void scan_kernel() {
    __shared__ int s[SCAN_T];
    __shared__ int s_tile;
    __shared__ int s_prefix;

    if (threadIdx.x == 0) s_tile = atomicAdd(&g_ticket, 1);
    __syncthreads();
    int tile = s_tile;
    int i = tile * SCAN_T + threadIdx.x;
    int v = (i < SEG) ? g_cnt[i] : 0;
    s[threadIdx.x] = v;
    __syncthreads();
    for (int d = 1; d < SCAN_T; d <<= 1) {
        int t = (threadIdx.x >= d) ? s[threadIdx.x - d] : 0;
        __syncthreads();
        s[threadIdx.x] += t;
        __syncthreads();
    }
    int incl  = s[threadIdx.x];
    int total = s[SCAN_T - 1];

    if (threadIdx.x == 0) {
        u64 st = (tile == 0) ? ((2ull << 32) | (unsigned)total)
                             : ((1ull << 32) | (unsigned)total);
        __threadfence();
        atomicExch(&g_state[tile], st);
        if (tile == 0) s_prefix = 0;
    }
    if (tile > 0 && threadIdx.x < 32) {
        int lane = threadIdx.x;
        int j = tile - 1;
        int agg = 0;
        while (true) {
            int idx = j - lane;
            u64 st = (idx >= 0) ? atomicAdd(&g_state[idx], 0ull) : (2ull << 32);
            unsigned flag = (unsigned)(st >> 32);
            unsigned invm = __ballot_sync(0xffffffffu, flag == 0);
            if (invm) continue;
            unsigned prefm = __ballot_sync(0xffffffffu, flag == 2);
            int stop = prefm ? (__ffs(prefm) - 1) : 32;
            int contrib = (lane <= stop) ? (int)(st & 0xffffffffu) : 0;
#pragma unroll
            for (int m = 16; m; m >>= 1) contrib += __shfl_xor_sync(~0u, contrib, m);
            agg += contrib;
            if (stop < 32) break;
            j -= 32;
        }
        if (lane == 0) {
            s_prefix = agg;
            __threadfence();
            atomicExch(&g_state[tile], (2ull << 32) | (unsigned)(agg + total));
        }
    }
    __syncthreads();
    int prefix = s_prefix;
    if (i < SEG) {
        int o = prefix + incl - v;
        g_off[i]  = o;
        g_fill[i] = o;
        g_inv[i]  = __fdividef(1.f, fmaxf((float)v, 1.f));
        g_cnt[i]  = 0;
    }
    if (i == SEG - 1) g_off[SEG] = N_EDGES;
}

// ---- 3. fill CSR; restore scan state ----
__global__ void fill_kernel(const int* __restrict__ src,
                            const int* __restrict__ dst,
                            const int* __restrict__ et) {
    int e = blockIdx.x * blockDim.x + threadIdx.x;
    if (e < N_EDGES) {
        int sg  = dst[e] * R + et[e];
        int pos = atomicAdd(&g_fill[sg], 1);
        g_esrc[pos] = src[e];
    }
    if (e < NT2) g_state[e] = 0ull;
    if (e == 0)  g_ticket = 0;
}

// ============================================================================
// Fused layer: cross-task pipelined relation-partitioned gather.
// Warp owns NPW contiguous nodes; offsets/invs preloaded into lane registers
// (shfl access); esrc batch for task t+1 prefetched during task t's x loads.
// ============================================================================
template <int DIN, int DOUT, int NB, bool RELU, bool POOL, int MINB>
__global__ __launch_bounds__(256, MINB) void layer_kernel(
        const float* __restrict__ xin,
        const float* __restrict__ W,
        const float* __restrict__ root,
        const float* __restrict__ bias,
        float* __restrict__ hout,
        const int* __restrict__ batch) {
    constexpr int F     = DIN / 8;            // floats per lane (2 or 4)
    constexpr int NU    = F / 2;              // u64 per lane (1 or 2)
    constexpr int NPW   = NB / 8;             // nodes per warp
    constexpr int OC    = DOUT / 4;
    constexpr int NGRP  = 256 / OC;
    constexpr int NPT   = NB / NGRP;
    constexpr int GSLOT = 8;
    static_assert(NB % 8 == 0 && NGRP * NPT == NB, "mapping");
    static_assert(F == 2 || F == 4, "lane feature width");
    static_assert(NPW * R <= 32, "offsets fit in one warp");

    __shared__ float    sAcc[NB][R + 1][DIN];
    __shared__ float    sW[(R + 1) * DIN * DOUT];
    __shared__ float    sBias[DOUT];
    __shared__ unsigned sPool[POOL ? GSLOT * 64 : 1];
    __shared__ int      sBatch[POOL ? NB : 1];

    for (int i = threadIdx.x; i < R * DIN * DOUT; i += 256) sW[i] = W[i];
    for (int i = threadIdx.x; i < DIN * DOUT; i += 256)
        sW[R * DIN * DOUT + i] = root[i];
    if (threadIdx.x < DOUT) sBias[threadIdx.x] = bias[threadIdx.x];

    const int node0 = blockIdx.x * NB;

    if (POOL) {
        for (int i = threadIdx.x; i < GSLOT * 64; i += 256) sPool[i] = 0u;
        if (threadIdx.x < NB) {
            int n = node0 + threadIdx.x;
            sBatch[threadIdx.x] = (n < N_NODES) ? batch[n] : 0;
        }
    }

    // ---- self rows (coalesced, outside the latency chain) ----
    for (int i = threadIdx.x; i < NB * (DIN / 2); i += 256) {
        int nn2 = i / (DIN / 2);
        int c   = i % (DIN / 2);
        int n2  = node0 + nn2;
        u64 v = (n2 < N_NODES)
              ? *reinterpret_cast<const u64*>(xin + n2 * DIN + c * 2) : 0ull;
        *reinterpret_cast<u64*>(&sAcc[nn2][R][c * 2]) = v;
    }

    const int wid   = threadIdx.x >> 5;
    const int lane  = threadIdx.x & 31;
    const int group = lane >> 3;              // relation 0..3
    const int fl    = lane & 7;               // feature sub-index

    // ---- preload this warp's offsets + invs into lane registers ----
    const int wnn     = wid * NPW;                  // first local node
    const int sb_base = (node0 + wnn) * R;
    int   o_l   = g_off[min(sb_base + lane, SEG)];
    int   extra = g_off[min(sb_base + NPW * R, SEG)];
    float inv_l = g_inv[min(sb_base + lane, SEG - 1)];

    // ---- pipelined task loop: task t = (node wnn+t, relation group) ----
    u64 acc[NU];
#pragma unroll
    for (int q = 0; q < NU; q++) acc[q] = 0ull;

    int o = __shfl_sync(~0u, o_l, group);
    int e = __shfl_sync(~0u, o_l, group + 1);
    int i0 = (o + 0 < e) ? g_esrc[o + 0] : -1;
    int i1 = (o + 1 < e) ? g_esrc[o + 1] : -1;
    int i2 = (o + 2 < e) ? g_esrc[o + 2] : -1;
    int i3 = (o + 3 < e) ? g_esrc[o + 3] : -1;

#pragma unroll
    for (int t = 0; t < NPW; t++) {
        // next task bounds (register shuffles, uniform flow)
        const bool hasNext = (t + 1 < NPW);
        int jn  = min((t + 1) * R + group, 31);
        int on  = __shfl_sync(~0u, o_l, jn);
        int ens = __shfl_sync(~0u, o_l, (jn + 1) & 31);
        int en  = (jn + 1 > NPW * R - 0 && jn == NPW * R + group - R) ? ens : ens;
        en = (jn == NPW * R - 1 + 0 && ((jn + 1) & 31) == 0) ? extra : ens;
        // cleaner: last segment's end is `extra` when jn+1 == NPW*R
        en = ((jn + 1) == NPW * R) ? extra : ens;

        // x loads for current task's first batch (critical path)
        u64 v0[NU], v1[NU], v2[NU], v3[NU];
        if (F == 2) {
            v0[0] = (i0 >= 0) ? *reinterpret_cast<const u64*>(xin + i0 * DIN + fl * 2) : 0ull;
            v1[0] = (i1 >= 0) ? *reinterpret_cast<const u64*>(xin + i1 * DIN + fl * 2) : 0ull;
            v2[0] = (i2 >= 0) ? *reinterpret_cast<const u64*>(xin + i2 * DIN + fl * 2) : 0ull;
            v3[0] = (i3 >= 0) ? *reinterpret_cast<const u64*>(xin + i3 * DIN + fl * 2) : 0ull;
        } else {
            ulonglong2 z = make_ulonglong2(0ull, 0ull);
            ulonglong2 a0 = (i0 >= 0) ? *reinterpret_cast<const ulonglong2*>(xin + i0 * DIN + fl * 4) : z;
            ulonglong2 a1 = (i1 >= 0) ? *reinterpret_cast<const ulonglong2*>(xin + i1 * DIN + fl * 4) : z;
            ulonglong2 a2 = (i2 >= 0) ? *reinterpret_cast<const ulonglong2*>(xin + i2 * DIN + fl * 4) : z;
            ulonglong2 a3 = (i3 >= 0) ? *reinterpret_cast<const ulonglong2*>(xin + i3 * DIN + fl * 4) : z;
            v0[0] = a0.x; v0[1] = a0.y; v1[0] = a1.x; v1[1] = a1.y;
            v2[0] = a2.x; v2[1] = a2.y; v3[0] = a3.x; v3[1] = a3.y;
        }

        // prefetch next task's first esrc batch (overlaps x loads above)
        int n0 = (hasNext && on + 0 < en) ? g_esrc[on + 0] : -1;
        int n1 = (hasNext && on + 1 < en) ? g_esrc[on + 1] : -1;
        int n2 = (hasNext && on + 2 < en) ? g_esrc[on + 2] : -1;
        int n3 = (hasNext && on + 3 < en) ? g_esrc[on + 3] : -1;

#pragma unroll
        for (int q = 0; q < NU; q++) {
            add2(acc[q], acc[q], v0[q]);
            add2(acc[q], acc[q], v1[q]);
            add2(acc[q], acc[q], v2[q]);
            add2(acc[q], acc[q], v3[q]);
        }

        // serial tail for degree > 4 (uncommon)
        for (int p = o + 4; p < e; p++) {
            int s = g_esrc[p];
            if (F == 2) {
                u64 v = *reinterpret_cast<const u64*>(xin + s * DIN + fl * 2);
                add2(acc[0], acc[0], v);
            } else {
                ulonglong2 v = *reinterpret_cast<const ulonglong2*>(xin + s * DIN + fl * 4);
                add2(acc[0], acc[0], v.x);
                add2(acc[1], acc[1], v.y);
            }
        }

        // normalize + store
        float invf = __shfl_sync(~0u, inv_l, t * R + group);
        u64 iv = pack2(invf);
        int nn = wnn + t;
        if (F == 2) {
            mul2(acc[0], acc[0], iv);
            *reinterpret_cast<u64*>(&sAcc[nn][group][fl * 2]) = acc[0];
        } else {
            mul2(acc[0], acc[0], iv);
            mul2(acc[1], acc[1], iv);
            *reinterpret_cast<ulonglong2*>(&sAcc[nn][group][fl * 4]) =
                make_ulonglong2(acc[0], acc[1]);
        }
#pragma unroll
        for (int q = 0; q < NU; q++) acc[q] = 0ull;

        // shift pipeline state
        o = on; e = en;
        i0 = n0; i1 = n1; i2 = n2; i3 = n3;
    }
    __syncthreads();

    // ---- transform (packed f32x2) ----
    {
        int oc  = threadIdx.x % OC;
        int grp = threadIdx.x / OC;
        int o0  = oc * 4;
        int nb0 = grp * NPT;

        const u64* bb = reinterpret_cast<const u64*>(&sBias[o0]);
        u64 s01[NPT], s23[NPT];
#pragma unroll
        for (int k = 0; k < NPT; k++) { s01[k] = bb[0]; s23[k] = bb[1]; }

#pragma unroll
        for (int r = 0; r < R + 1; r++) {
#pragma unroll
            for (int i4 = 0; i4 < DIN / 4; i4++) {
                const float* wb = &sW[(r * DIN + i4 * 4) * DOUT + o0];
                ulonglong2 w0 = *reinterpret_cast<const ulonglong2*>(wb);
                ulonglong2 w1 = *reinterpret_cast<const ulonglong2*>(wb + DOUT);
                ulonglong2 w2 = *reinterpret_cast<const ulonglong2*>(wb + 2 * DOUT);
                ulonglong2 w3 = *reinterpret_cast<const ulonglong2*>(wb + 3 * DOUT);
#pragma unroll
                for (int k = 0; k < NPT; k++) {
                    float4 a = *reinterpret_cast<const float4*>(&sAcc[nb0 + k][r][i4 * 4]);
                    u64 aa;
                    aa = pack2(a.x); fma2(s01[k], aa, w0.x, s01[k]); fma2(s23[k], aa, w0.y, s23[k]);
                    aa = pack2(a.y); fma2(s01[k], aa, w1.x, s01[k]); fma2(s23[k], aa, w1.y, s23[k]);
                    aa = pack2(a.z); fma2(s01[k], aa, w2.x, s01[k]); fma2(s23[k], aa, w2.y, s23[k]);
                    aa = pack2(a.w); fma2(s01[k], aa, w3.x, s01[k]); fma2(s23[k], aa, w3.y, s23[k]);
                }
            }
        }
#pragma unroll
        for (int k = 0; k < NPT; k++) {
            int n = node0 + nb0 + k;
            if (n < N_NODES) {
                union { u64 q[2]; float f[4]; } sv;
                sv.q[0] = s01[k]; sv.q[1] = s23[k];
                if (RELU) {
#pragma unroll
                    for (int j = 0; j < 4; j++) sv.f[j] = fmaxf(sv.f[j], 0.f);
                }
                if (!POOL) {
                    *reinterpret_cast<float4*>(&hout[n * DOUT + o0]) =
                        make_float4(sv.f[0], sv.f[1], sv.f[2], sv.f[3]);
                } else {
                    int g  = sBatch[nb0 + k];
                    int gr = g - sBatch[0];
#pragma unroll
                    for (int j = 0; j < 4; j++) {
                        unsigned ev = enc(sv.f[j]);
                        if (gr < GSLOT)
                            atomicMax(&sPool[gr * 64 + o0 + j], ev);
                        else
                            atomicMax(&g_pool[g * 64 + o0 + j], ev);
                    }
                }
            }
        }
    }

    if (POOL) {
        __syncthreads();
        int g0 = sBatch[0];
        for (int i = threadIdx.x; i < GSLOT * 64; i += 256) {
            unsigned v = sPool[i];
            int g = g0 + i / 64;
            if (v != 0u && g < NG)
                atomicMax(&g_pool[g * 64 + (i & 63)], v);
        }
    }
}

// ---- decode + restore pool ----
__global__ void decode_kernel(float* __restrict__ out) {
    int i = blockIdx.x * blockDim.x + threadIdx.x;
    if (i < NG * 64) {
        unsigned u = g_pool[i];
        out[i] = (u == 0u) ? __int_as_float(0xff800000) : dec(u);
        g_pool[i] = 0u;
    }
}

extern "C" void kernel_launch(void* const* d_in, const int* in_sizes, int n_in,
                              void* d_out, int out_size) {
    const float* x     = (const float*)d_in[0];
    const int*   ei    = (const int*)d_in[1];
    const int*   src   = ei;
    const int*   dst   = ei + N_EDGES;
    const int*   et    = (const int*)d_in[2];
    const int*   batch = (const int*)d_in[3];
    const float* W1 = (const float*)d_in[4];
    const float* r1 = (const float*)d_in[5];
    const float* b1 = (const float*)d_in[6];
    const float* W2 = (const float*)d_in[7];
    const float* r2 = (const float*)d_in[8];
    const float* b2 = (const float*)d_in[9];
    const float* W3 = (const float*)d_in[10];
    const float* r3 = (const float*)d_in[11];
    const float* b3 = (const float*)d_in[12];
    float* out = (float*)d_out;

    float *h1p, *h2p;
    cudaGetSymbolAddress((void**)&h1p, g_h1);
    cudaGetSymbolAddress((void**)&h2p, g_h2);

    const int T = 256;

    count_kernel<<<(N_EDGES + T - 1) / T, T>>>(dst, et);         // 1
    scan_kernel<<<NT2, SCAN_T>>>();                              // 2
    fill_kernel<<<(N_EDGES + T - 1) / T, T>>>(src, dst, et);     // 3

    layer_kernel<16, 16, 64, true,  false, 4>                    // 4 <- profiled
        <<<(N_NODES + 63) / 64, T>>>(x,   W1, r1, b1, h1p, nullptr);
    layer_kernel<16, 32, 64, true,  false, 4>
        <<<(N_NODES + 63) / 64, T>>>(h1p, W2, r2, b2, h2p, nullptr);
    layer_kernel<32, 64, 32, false, true,  3>
        <<<(N_NODES + 31) / 32, T>>>(h2p, W3, r3, b3, nullptr, batch);

    decode_kernel<<<(NG * 64 + T - 1) / T, T>>>(out);
}

// round 12
// speedup vs baseline: 1.4923x; 1.0520x over previous
#include <cuda_runtime.h>

#define N_NODES 100000
#define N_EDGES 1600000
#define R 4
#define NG 256
#define SEG (N_NODES * R)
#define SCAN_T 1024
#define NT2 ((SEG + SCAN_T - 1) / SCAN_T)

typedef unsigned long long u64;

// ---- scratch (zero-init at module load; launches self-restore) ----
__device__ int      g_cnt[SEG];
__device__ int      g_off[SEG + 1];
__device__ int      g_fill[SEG];
__device__ float    g_inv[SEG];
__device__ int      g_esrc[N_EDGES];
__device__ u64      g_state[NT2];
__device__ int      g_ticket;
__device__ float    g_h1[N_NODES * 16];
__device__ float    g_h2[N_NODES * 32];
__device__ unsigned g_pool[NG * 64];

// ---- packed f32x2 helpers ----
__device__ __forceinline__ void fma2(u64& d, u64 a, u64 b, u64 c) {
    asm("fma.rn.f32x2 %0, %1, %2, %3;" : "=l"(d) : "l"(a), "l"(b), "l"(c));
}
__device__ __forceinline__ void add2(u64& d, u64 a, u64 b) {
    asm("add.rn.f32x2 %0, %1, %2;" : "=l"(d) : "l"(a), "l"(b));
}
__device__ __forceinline__ void mul2(u64& d, u64 a, u64 b) {
    asm("mul.rn.f32x2 %0, %1, %2;" : "=l"(d) : "l"(a), "l"(b));
}
__device__ __forceinline__ u64 pack2(float x) {
    u64 d; unsigned u = __float_as_uint(x);
    asm("mov.b64 %0, {%1, %1};" : "=l"(d) : "r"(u));
    return d;
}

__device__ __forceinline__ unsigned enc(float v) {
    unsigned u = __float_as_uint(v);
    return (u & 0x80000000u) ? ~u : (u | 0x80000000u);
}
__device__ __forceinline__ float dec(unsigned u) {
    unsigned bits = (u & 0x80000000u) ? (u ^ 0x80000000u) : ~u;
    return __uint_as_float(bits);
}

// ---- 1. count ----
__global__ void count_kernel(const int* __restrict__ dst,
                             const int* __restrict__ et) {
    int e = blockIdx.x * blockDim.x + threadIdx.x;
    if (e < N_EDGES) atomicAdd(&g_cnt[dst[e] * R + et[e]], 1);
}

// ---- 2. decoupled-lookback scan; seeds off/fill/inv; zeroes cnt ----
__global__ __launch_bounds__(SCAN_T) void scan_kernel() {
    __shared__ int s[SCAN_T];
    __shared__ int s_tile;
    __shared__ int s_prefix;

    if (threadIdx.x == 0) s_tile = atomicAdd(&g_ticket, 1);
    __syncthreads();
    int tile = s_tile;
    int i = tile * SCAN_T + threadIdx.x;
    int v = (i < SEG) ? g_cnt[i] : 0;
    s[threadIdx.x] = v;
    __syncthreads();
    for (int d = 1; d < SCAN_T; d <<= 1) {
        int t = (threadIdx.x >= d) ? s[threadIdx.x - d] : 0;
        __syncthreads();
        s[threadIdx.x] += t;
        __syncthreads();
    }
    int incl  = s[threadIdx.x];
    int total = s[SCAN_T - 1];

    if (threadIdx.x == 0) {
        u64 st = (tile == 0) ? ((2ull << 32) | (unsigned)total)
                             : ((1ull << 32) | (unsigned)total);
        __threadfence();
        atomicExch(&g_state[tile], st);
        if (tile == 0) s_prefix = 0;
    }
    if (tile > 0 && threadIdx.x < 32) {
        int lane = threadIdx.x;
        int j = tile - 1;
        int agg = 0;
        while (true) {
            int idx = j - lane;
            u64 st = (idx >= 0) ? atomicAdd(&g_state[idx], 0ull) : (2ull << 32);
            unsigned flag = (unsigned)(st >> 32);
            unsigned invm = __ballot_sync(0xffffffffu, flag == 0);
            if (invm) continue;
            unsigned prefm = __ballot_sync(0xffffffffu, flag == 2);
            int stop = prefm ? (__ffs(prefm) - 1) : 32;
            int contrib = (lane <= stop) ? (int)(st & 0xffffffffu) : 0;
#pragma unroll
            for (int m = 16; m; m >>= 1) contrib += __shfl_xor_sync(~0u, contrib, m);
            agg += contrib;
            if (stop < 32) break;
            j -= 32;
        }
        if (lane == 0) {
            s_prefix = agg;
            __threadfence();
            atomicExch(&g_state[tile], (2ull << 32) | (unsigned)(agg + total));
        }
    }
    __syncthreads();
    int prefix = s_prefix;
    if (i < SEG) {
        int o = prefix + incl - v;
        g_off[i]  = o;
        g_fill[i] = o;
        g_inv[i]  = __fdividef(1.f, fmaxf((float)v, 1.f));
        g_cnt[i]  = 0;
    }
    if (i == SEG - 1) g_off[SEG] = N_EDGES;
}

// ---- 3. fill CSR; restore scan state ----
__global__ void fill_kernel(const int* __restrict__ src,
                            const int* __restrict__ dst,
                            const int* __restrict__ et) {
    int e = blockIdx.x * blockDim.x + threadIdx.x;
    if (e < N_EDGES) {
        int sg  = dst[e] * R + et[e];
        int pos = atomicAdd(&g_fill[sg], 1);
        g_esrc[pos] = src[e];
    }
    if (e < NT2) g_state[e] = 0ull;
    if (e == 0)  g_ticket = 0;
}

// ============================================================================
// Fused layer (round-9 structure): cross-task pipelined relation-partitioned
// gather + batched deg>4 tail.  POOL fuses segment-max pooling.
// ============================================================================
template <int DIN, int DOUT, int NB, bool RELU, bool POOL, int MINB>
__global__ __launch_bounds__(256, MINB) void layer_kernel(
        const float* __restrict__ xin,
        const float* __restrict__ W,
        const float* __restrict__ root,
        const float* __restrict__ bias,
        float* __restrict__ hout,
        const int* __restrict__ batch) {
    constexpr int F     = DIN / 8;            // floats per lane (2 or 4)
    constexpr int NU    = F / 2;              // u64 per lane (1 or 2)
    constexpr int NPW   = NB / 8;             // nodes per warp
    constexpr int OC    = DOUT / 4;
    constexpr int NGRP  = 256 / OC;
    constexpr int NPT   = NB / NGRP;
    constexpr int GSLOT = 8;
    static_assert(NB % 8 == 0 && NGRP * NPT == NB, "mapping");
    static_assert(F == 2 || F == 4, "lane feature width");
    static_assert(NPW * R <= 32, "offsets fit in one warp");

    __shared__ float    sAcc[NB][R + 1][DIN];
    __shared__ float    sW[(R + 1) * DIN * DOUT];
    __shared__ float    sBias[DOUT];
    __shared__ unsigned sPool[POOL ? GSLOT * 64 : 1];
    __shared__ int      sBatch[POOL ? NB : 1];

    for (int i = threadIdx.x; i < R * DIN * DOUT; i += 256) sW[i] = W[i];
    for (int i = threadIdx.x; i < DIN * DOUT; i += 256)
        sW[R * DIN * DOUT + i] = root[i];
    if (threadIdx.x < DOUT) sBias[threadIdx.x] = bias[threadIdx.x];

    const int node0 = blockIdx.x * NB;

    if (POOL) {
        for (int i = threadIdx.x; i < GSLOT * 64; i += 256) sPool[i] = 0u;
        if (threadIdx.x < NB) {
            int n = node0 + threadIdx.x;
            sBatch[threadIdx.x] = (n < N_NODES) ? batch[n] : 0;
        }
    }

    // ---- self rows (coalesced, outside the latency chain) ----
    for (int i = threadIdx.x; i < NB * (DIN / 2); i += 256) {
        int nn2 = i / (DIN / 2);
        int c   = i % (DIN / 2);
        int n2  = node0 + nn2;
        u64 v = (n2 < N_NODES)
              ? *reinterpret_cast<const u64*>(xin + n2 * DIN + c * 2) : 0ull;
        *reinterpret_cast<u64*>(&sAcc[nn2][R][c * 2]) = v;
    }

    const int wid   = threadIdx.x >> 5;
    const int lane  = threadIdx.x & 31;
    const int group = lane >> 3;              // relation 0..3
    const int fl    = lane & 7;               // feature sub-index

    // ---- preload this warp's offsets + invs into lane registers ----
    const int wnn     = wid * NPW;
    const int sb_base = (node0 + wnn) * R;
    int   o_l   = g_off[min(sb_base + lane, SEG)];
    int   extra = g_off[min(sb_base + NPW * R, SEG)];
    float inv_l = g_inv[min(sb_base + lane, SEG - 1)];

    // ---- pipelined task loop: task t = (node wnn+t, relation group) ----
    u64 acc[NU];
#pragma unroll
    for (int q = 0; q < NU; q++) acc[q] = 0ull;

    int o = __shfl_sync(~0u, o_l, group);
    int e = __shfl_sync(~0u, o_l, group + 1);
    int i0 = (o + 0 < e) ? g_esrc[o + 0] : -1;
    int i1 = (o + 1 < e) ? g_esrc[o + 1] : -1;
    int i2 = (o + 2 < e) ? g_esrc[o + 2] : -1;
    int i3 = (o + 3 < e) ? g_esrc[o + 3] : -1;

#pragma unroll
    for (int t = 0; t < NPW; t++) {
        // next task bounds (register shuffles, uniform flow)
        const bool hasNext = (t + 1 < NPW);
        int jn  = min((t + 1) * R + group, 31);
        int on  = __shfl_sync(~0u, o_l, jn);
        int ens = __shfl_sync(~0u, o_l, (jn + 1) & 31);
        int en  = ((jn + 1) == NPW * R) ? extra : ens;

        // x loads for current task's first batch (critical path)
        u64 v0[NU], v1[NU], v2[NU], v3[NU];
        if (F == 2) {
            v0[0] = (i0 >= 0) ? *reinterpret_cast<const u64*>(xin + i0 * DIN + fl * 2) : 0ull;
            v1[0] = (i1 >= 0) ? *reinterpret_cast<const u64*>(xin + i1 * DIN + fl * 2) : 0ull;
            v2[0] = (i2 >= 0) ? *reinterpret_cast<const u64*>(xin + i2 * DIN + fl * 2) : 0ull;
            v3[0] = (i3 >= 0) ? *reinterpret_cast<const u64*>(xin + i3 * DIN + fl * 2) : 0ull;
        } else {
            ulonglong2 z = make_ulonglong2(0ull, 0ull);
            ulonglong2 a0 = (i0 >= 0) ? *reinterpret_cast<const ulonglong2*>(xin + i0 * DIN + fl * 4) : z;
            ulonglong2 a1 = (i1 >= 0) ? *reinterpret_cast<const ulonglong2*>(xin + i1 * DIN + fl * 4) : z;
            ulonglong2 a2 = (i2 >= 0) ? *reinterpret_cast<const ulonglong2*>(xin + i2 * DIN + fl * 4) : z;
            ulonglong2 a3 = (i3 >= 0) ? *reinterpret_cast<const ulonglong2*>(xin + i3 * DIN + fl * 4) : z;
            v0[0] = a0.x; v0[1] = a0.y; v1[0] = a1.x; v1[1] = a1.y;
            v2[0] = a2.x; v2[1] = a2.y; v3[0] = a3.x; v3[1] = a3.y;
        }

        // prefetch next task's first esrc batch (overlaps x loads above)
        int n0 = (hasNext && on + 0 < en) ? g_esrc[on + 0] : -1;
        int n1 = (hasNext && on + 1 < en) ? g_esrc[on + 1] : -1;
        int n2 = (hasNext && on + 2 < en) ? g_esrc[on + 2] : -1;
        int n3 = (hasNext && on + 3 < en) ? g_esrc[on + 3] : -1;

#pragma unroll
        for (int q = 0; q < NU; q++) {
            add2(acc[q], acc[q], v0[q]);
            add2(acc[q], acc[q], v1[q]);
            add2(acc[q], acc[q], v2[q]);
            add2(acc[q], acc[q], v3[q]);
        }

        // batched tail for degree > 4 (groups of 4, proven guard pattern)
        for (int p = o + 4; p < e; p += 4) {
            int t0 = (p + 0 < e) ? g_esrc[p + 0] : -1;
            int t1 = (p + 1 < e) ? g_esrc[p + 1] : -1;
            int t2 = (p + 2 < e) ? g_esrc[p + 2] : -1;
            int t3 = (p + 3 < e) ? g_esrc[p + 3] : -1;
            if (F == 2) {
                u64 x0 = (t0 >= 0) ? *reinterpret_cast<const u64*>(xin + t0 * DIN + fl * 2) : 0ull;
                u64 x1 = (t1 >= 0) ? *reinterpret_cast<const u64*>(xin + t1 * DIN + fl * 2) : 0ull;
                u64 x2 = (t2 >= 0) ? *reinterpret_cast<const u64*>(xin + t2 * DIN + fl * 2) : 0ull;
                u64 x3 = (t3 >= 0) ? *reinterpret_cast<const u64*>(xin + t3 * DIN + fl * 2) : 0ull;
                add2(acc[0], acc[0], x0); add2(acc[0], acc[0], x1);
                add2(acc[0], acc[0], x2); add2(acc[0], acc[0], x3);
            } else {
                ulonglong2 z = make_ulonglong2(0ull, 0ull);
                ulonglong2 x0 = (t0 >= 0) ? *reinterpret_cast<const ulonglong2*>(xin + t0 * DIN + fl * 4) : z;
                ulonglong2 x1 = (t1 >= 0) ? *reinterpret_cast<const ulonglong2*>(xin + t1 * DIN + fl * 4) : z;
                ulonglong2 x2 = (t2 >= 0) ? *reinterpret_cast<const ulonglong2*>(xin + t2 * DIN + fl * 4) : z;
                ulonglong2 x3 = (t3 >= 0) ? *reinterpret_cast<const ulonglong2*>(xin + t3 * DIN + fl * 4) : z;
                add2(acc[0], acc[0], x0.x); add2(acc[1], acc[1], x0.y);
                add2(acc[0], acc[0], x1.x); add2(acc[1], acc[1], x1.y);
                add2(acc[0], acc[0], x2.x); add2(acc[1], acc[1], x2.y);
                add2(acc[0], acc[0], x3.x); add2(acc[1], acc[1], x3.y);
            }
        }

        // normalize + store
        float invf = __shfl_sync(~0u, inv_l, t * R + group);
        u64 iv = pack2(invf);
        int nn = wnn + t;
        if (F == 2) {
            mul2(acc[0], acc[0], iv);
            *reinterpret_cast<u64*>(&sAcc[nn][group][fl * 2]) = acc[0];
        } else {
            mul2(acc[0], acc[0], iv);
            mul2(acc[1], acc[1], iv);
            *reinterpret_cast<ulonglong2*>(&sAcc[nn][group][fl * 4]) =
                make_ulonglong2(acc[0], acc[1]);
        }
#pragma unroll
        for (int q = 0; q < NU; q++) acc[q] = 0ull;

        // shift pipeline state
        o = on; e = en;
        i0 = n0; i1 = n1; i2 = n2; i3 = n3;
    }
    __syncthreads();

    // ---- transform (packed f32x2) ----
    {
        int oc  = threadIdx.x % OC;
        int grp = threadIdx.x / OC;
        int o0  = oc * 4;
        int nb0 = grp * NPT;

        const u64* bb = reinterpret_cast<const u64*>(&sBias[o0]);
        u64 s01[NPT], s23[NPT];
#pragma unroll
        for (int k = 0; k < NPT; k++) { s01[k] = bb[0]; s23[k] = bb[1]; }

#pragma unroll
        for (int r = 0; r < R + 1; r++) {
#pragma unroll
            for (int i4 = 0; i4 < DIN / 4; i4++) {
                const float* wb = &sW[(r * DIN + i4 * 4) * DOUT + o0];
                ulonglong2 w0 = *reinterpret_cast<const ulonglong2*>(wb);
                ulonglong2 w1 = *reinterpret_cast<const ulonglong2*>(wb + DOUT);
                ulonglong2 w2 = *reinterpret_cast<const ulonglong2*>(wb + 2 * DOUT);
                ulonglong2 w3 = *reinterpret_cast<const ulonglong2*>(wb + 3 * DOUT);
#pragma unroll
                for (int k = 0; k < NPT; k++) {
                    float4 a = *reinterpret_cast<const float4*>(&sAcc[nb0 + k][r][i4 * 4]);
                    u64 aa;
                    aa = pack2(a.x); fma2(s01[k], aa, w0.x, s01[k]); fma2(s23[k], aa, w0.y, s23[k]);
                    aa = pack2(a.y); fma2(s01[k], aa, w1.x, s01[k]); fma2(s23[k], aa, w1.y, s23[k]);
                    aa = pack2(a.z); fma2(s01[k], aa, w2.x, s01[k]); fma2(s23[k], aa, w2.y, s23[k]);
                    aa = pack2(a.w); fma2(s01[k], aa, w3.x, s01[k]); fma2(s23[k], aa, w3.y, s23[k]);
                }
            }
        }
#pragma unroll
        for (int k = 0; k < NPT; k++) {
            int n = node0 + nb0 + k;
            if (n < N_NODES) {
                union { u64 q[2]; float f[4]; } sv;
                sv.q[0] = s01[k]; sv.q[1] = s23[k];
                if (RELU) {
#pragma unroll
                    for (int j = 0; j < 4; j++) sv.f[j] = fmaxf(sv.f[j], 0.f);
                }
                if (!POOL) {
                    *reinterpret_cast<float4*>(&hout[n * DOUT + o0]) =
                        make_float4(sv.f[0], sv.f[1], sv.f[2], sv.f[3]);
                } else {
                    int g  = sBatch[nb0 + k];
                    int gr = g - sBatch[0];
#pragma unroll
                    for (int j = 0; j < 4; j++) {
                        unsigned ev = enc(sv.f[j]);
                        if (gr >= 0 && gr < GSLOT)
                            atomicMax(&sPool[gr * 64 + o0 + j], ev);
                        else
                            atomicMax(&g_pool[g * 64 + o0 + j], ev);
                    }
                }
            }
        }
    }

    if (POOL) {
        __syncthreads();
        int g0 = sBatch[0];
        for (int i = threadIdx.x; i < GSLOT * 64; i += 256) {
            unsigned v = sPool[i];
            int g = g0 + i / 64;
            if (v != 0u && g < NG)
                atomicMax(&g_pool[g * 64 + (i & 63)], v);
        }
    }
}

// ---- decode + restore pool ----
__global__ void decode_kernel(float* __restrict__ out) {
    int i = blockIdx.x * blockDim.x + threadIdx.x;
    if (i < NG * 64) {
        unsigned u = g_pool[i];
        out[i] = (u == 0u) ? __int_as_float(0xff800000) : dec(u);
        g_pool[i] = 0u;
    }
}

extern "C" void kernel_launch(void* const* d_in, const int* in_sizes, int n_in,
                              void* d_out, int out_size) {
    const float* x     = (const float*)d_in[0];
    const int*   ei    = (const int*)d_in[1];
    const int*   src   = ei;
    const int*   dst   = ei + N_EDGES;
    const int*   et    = (const int*)d_in[2];
    const int*   batch = (const int*)d_in[3];
    const float* W1 = (const float*)d_in[4];
    const float* r1 = (const float*)d_in[5];
    const float* b1 = (const float*)d_in[6];
    const float* W2 = (const float*)d_in[7];
    const float* r2 = (const float*)d_in[8];
    const float* b2 = (const float*)d_in[9];
    const float* W3 = (const float*)d_in[10];
    const float* r3 = (const float*)d_in[11];
    const float* b3 = (const float*)d_in[12];
    float* out = (float*)d_out;

    float *h1p, *h2p;
    cudaGetSymbolAddress((void**)&h1p, g_h1);
    cudaGetSymbolAddress((void**)&h2p, g_h2);

    const int T = 256;

    count_kernel<<<(N_EDGES + T - 1) / T, T>>>(dst, et);         // 1
    scan_kernel<<<NT2, SCAN_T>>>();                              // 2
    fill_kernel<<<(N_EDGES + T - 1) / T, T>>>(src, dst, et);     // 3

    layer_kernel<16, 16, 64, true,  false, 4>                    // 4 <- profiled
        <<<(N_NODES + 63) / 64, T>>>(x,   W1, r1, b1, h1p, nullptr);
    layer_kernel<16, 32, 64, true,  false, 4>
        <<<(N_NODES + 63) / 64, T>>>(h1p, W2, r2, b2, h2p, nullptr);
    layer_kernel<32, 64, 32, false, true,  3>
        <<<(N_NODES + 31) / 32, T>>>(h2p, W3, r3, b3, nullptr, batch);

    decode_kernel<<<(NG * 64 + T - 1) / T, T>>>(out);
}